// round 2
// baseline (speedup 1.0000x reference)
#include <cuda_runtime.h>
#include <math.h>

#define BATCH 4
#define SEQ   4096
#define DIM   768

// Scratch (allocation-free rule: __device__ globals)
__device__ float g_q[(size_t)BATCH * SEQ * DIM];
__device__ float g_k[(size_t)BATCH * SEQ * DIM];
__device__ float g_v[(size_t)BATCH * SEQ * DIM];
__device__ float g_s[(size_t)BATCH * SEQ * SEQ];

// ---------------------------------------------------------------------------
// Canonical 128x128x8 fp32 SGEMM, 256 threads, 8x8 micro-tile (4+4 split).
// BT=true : C = A[M,K] * B[N,K]^T   (NT)
// BT=false: C = A[M,K] * B[K,N]     (NN)
// C = alpha * (A op(B)) + bias (bias optional, per-column)
// blockIdx.z batches via byte-element strides sA/sB/sC.
// Requires: M%128==0, N%128==0, K%8==0, all pointers 16B aligned rows.
// ---------------------------------------------------------------------------
template <bool BT>
__global__ __launch_bounds__(256) void sgemm_k(
    const float* __restrict__ A, const float* __restrict__ Bm,
    const float* __restrict__ bias, float* __restrict__ C,
    int M, int N, int K, float alpha,
    size_t sA, size_t sB, size_t sC)
{
    __shared__ float As[8][128];
    __shared__ float Bs[8][128];

    const int z = blockIdx.z;
    A  += (size_t)z * sA;
    Bm += (size_t)z * sB;
    C  += (size_t)z * sC;

    const int tid = threadIdx.x;
    const int tx  = tid & 15;        // 0..15 -> N micro position
    const int ty  = tid >> 4;        // 0..15 -> M micro position
    const int m0  = blockIdx.x * 128;
    const int n0  = blockIdx.y * 128;

    // Loader indices: 128x8 tile as 256 threads * float4
    const int la_r = tid >> 1;            // 0..127
    const int la_c = (tid & 1) * 4;       // 0 or 4
    // NN B loader: 8x128 tile
    const int lb_r = tid >> 5;            // 0..7
    const int lb_c = (tid & 31) * 4;      // 0..124

    float acc[2][2][4][4];
#pragma unroll
    for (int a = 0; a < 2; a++)
#pragma unroll
        for (int b = 0; b < 2; b++)
#pragma unroll
            for (int i = 0; i < 4; i++)
#pragma unroll
                for (int j = 0; j < 4; j++) acc[a][b][i][j] = 0.0f;

    const float* Aptr = A + (size_t)(m0 + la_r) * K + la_c;
    const float* Bptr;
    if (BT) Bptr = Bm + (size_t)(n0 + la_r) * K + la_c;
    else    Bptr = Bm + (size_t)lb_r * N + n0 + lb_c;

    for (int k0 = 0; k0 < K; k0 += 8) {
        float4 av = *(const float4*)Aptr;
        Aptr += 8;
        As[la_c + 0][la_r] = av.x;
        As[la_c + 1][la_r] = av.y;
        As[la_c + 2][la_r] = av.z;
        As[la_c + 3][la_r] = av.w;

        if (BT) {
            float4 bv = *(const float4*)Bptr;
            Bptr += 8;
            Bs[la_c + 0][la_r] = bv.x;
            Bs[la_c + 1][la_r] = bv.y;
            Bs[la_c + 2][la_r] = bv.z;
            Bs[la_c + 3][la_r] = bv.w;
        } else {
            float4 bv = *(const float4*)Bptr;
            Bptr += (size_t)8 * N;
            *(float4*)&Bs[lb_r][lb_c] = bv;
        }
        __syncthreads();

#pragma unroll
        for (int k = 0; k < 8; k++) {
            float4 a0 = *(const float4*)&As[k][ty * 4];
            float4 a1 = *(const float4*)&As[k][ty * 4 + 64];
            float4 b0 = *(const float4*)&Bs[k][tx * 4];
            float4 b1 = *(const float4*)&Bs[k][tx * 4 + 64];
            float ar[2][4] = {{a0.x, a0.y, a0.z, a0.w}, {a1.x, a1.y, a1.z, a1.w}};
            float br[2][4] = {{b0.x, b0.y, b0.z, b0.w}, {b1.x, b1.y, b1.z, b1.w}};
#pragma unroll
            for (int ih = 0; ih < 2; ih++)
#pragma unroll
                for (int jh = 0; jh < 2; jh++)
#pragma unroll
                    for (int i = 0; i < 4; i++)
#pragma unroll
                        for (int j = 0; j < 4; j++)
                            acc[ih][jh][i][j] =
                                fmaf(ar[ih][i], br[jh][j], acc[ih][jh][i][j]);
        }
        __syncthreads();
    }

    // Epilogue: alpha scale (+ optional per-column bias), vectorized stores.
#pragma unroll
    for (int ih = 0; ih < 2; ih++)
#pragma unroll
        for (int i = 0; i < 4; i++) {
            const int row = m0 + ih * 64 + ty * 4 + i;
#pragma unroll
            for (int jh = 0; jh < 2; jh++) {
                const int col = n0 + jh * 64 + tx * 4;
                float4 o;
                o.x = acc[ih][jh][i][0] * alpha;
                o.y = acc[ih][jh][i][1] * alpha;
                o.z = acc[ih][jh][i][2] * alpha;
                o.w = acc[ih][jh][i][3] * alpha;
                if (bias) {
                    float4 bb = *(const float4*)(bias + col);
                    o.x += bb.x; o.y += bb.y; o.z += bb.z; o.w += bb.w;
                }
                *(float4*)(C + (size_t)row * N + col) = o;
            }
        }
}

// ---------------------------------------------------------------------------
// Row softmax over 4096 columns, one block (256 thr) per row, data stays in
// registers (4x float4 per thread).
// ---------------------------------------------------------------------------
__global__ __launch_bounds__(256) void softmax_k(float* __restrict__ S)
{
    float* p = S + (size_t)blockIdx.x * SEQ;
    const int tid = threadIdx.x;

    float4 v[4];
#pragma unroll
    for (int i = 0; i < 4; i++) v[i] = *(const float4*)(p + tid * 4 + i * 1024);

    float m = -INFINITY;
#pragma unroll
    for (int i = 0; i < 4; i++) {
        m = fmaxf(m, fmaxf(fmaxf(v[i].x, v[i].y), fmaxf(v[i].z, v[i].w)));
    }

    __shared__ float red[256];
    red[tid] = m;
    __syncthreads();
#pragma unroll
    for (int s = 128; s > 0; s >>= 1) {
        if (tid < s) red[tid] = fmaxf(red[tid], red[tid + s]);
        __syncthreads();
    }
    m = red[0];
    __syncthreads();

    float sum = 0.0f;
#pragma unroll
    for (int i = 0; i < 4; i++) {
        v[i].x = __expf(v[i].x - m);
        v[i].y = __expf(v[i].y - m);
        v[i].z = __expf(v[i].z - m);
        v[i].w = __expf(v[i].w - m);
        sum += v[i].x + v[i].y + v[i].z + v[i].w;
    }

    red[tid] = sum;
    __syncthreads();
#pragma unroll
    for (int s = 128; s > 0; s >>= 1) {
        if (tid < s) red[tid] += red[tid + s];
        __syncthreads();
    }
    const float inv = 1.0f / red[0];

#pragma unroll
    for (int i = 0; i < 4; i++) {
        v[i].x *= inv; v[i].y *= inv; v[i].z *= inv; v[i].w *= inv;
        *(float4*)(p + tid * 4 + i * 1024) = v[i];
    }
}

// ---------------------------------------------------------------------------
extern "C" void kernel_launch(void* const* d_in, const int* in_sizes, int n_in,
                              void* d_out, int out_size)
{
    const float* x  = (const float*)d_in[0];
    const float* Wq = (const float*)d_in[1];
    const float* bq = (const float*)d_in[2];
    const float* Wk = (const float*)d_in[3];
    const float* bk = (const float*)d_in[4];
    const float* Wv = (const float*)d_in[5];
    const float* bv = (const float*)d_in[6];
    float* out = (float*)d_out;

    float *q, *k, *v, *s;
    cudaGetSymbolAddress((void**)&q, g_q);
    cudaGetSymbolAddress((void**)&k, g_k);
    cudaGetSymbolAddress((void**)&v, g_v);
    cudaGetSymbolAddress((void**)&s, g_s);

    const float scale = 1.0f / sqrtf((float)DIM);
    const int M = BATCH * SEQ;                  // 16384

    dim3 blk(256);

    // QKV projections: [16384,768] = x[16384,768] * W[768,768]^T + b
    sgemm_k<true><<<dim3(M / 128, DIM / 128, 1), blk>>>(
        x, Wq, bq, q, M, DIM, DIM, 1.0f, 0, 0, 0);
    sgemm_k<true><<<dim3(M / 128, DIM / 128, 1), blk>>>(
        x, Wk, bk, k, M, DIM, DIM, 1.0f, 0, 0, 0);
    sgemm_k<true><<<dim3(M / 128, DIM / 128, 1), blk>>>(
        x, Wv, bv, v, M, DIM, DIM, 1.0f, 0, 0, 0);

    // scores[b] = scale * Q[b] * K[b]^T   (per batch via blockIdx.z)
    sgemm_k<true><<<dim3(SEQ / 128, SEQ / 128, BATCH), blk>>>(
        q, k, nullptr, s, SEQ, SEQ, DIM, scale,
        (size_t)SEQ * DIM, (size_t)SEQ * DIM, (size_t)SEQ * SEQ);

    // row softmax over last axis
    softmax_k<<<BATCH * SEQ, blk>>>(s);

    // out[b] = P[b] * V[b]
    sgemm_k<false><<<dim3(SEQ / 128, DIM / 128, BATCH), blk>>>(
        s, v, nullptr, out, SEQ, DIM, SEQ, 1.0f,
        (size_t)SEQ * SEQ, (size_t)SEQ * DIM, (size_t)SEQ * DIM);

    (void)in_sizes; (void)n_in; (void)out_size;
}

// round 5
// speedup vs baseline: 1.8305x; 1.8305x over previous
#include <cuda_runtime.h>
#include <cuda_bf16.h>
#include <mma.h>
#include <cstdint>
#include <math.h>

using namespace nvcuda;
using bf16 = __nv_bfloat16;

#define BATCH 4
#define SEQ   4096
#define DIM   768
#define NTOK  (BATCH * SEQ)                 // 16384
#define NTD   ((size_t)NTOK * DIM)
#define WSZ   ((size_t)DIM * DIM)
#define SSZ   ((size_t)BATCH * SEQ * SEQ)

// ---------------- device scratch (allocation-free rule) ----------------
__device__ bf16  g_xh[NTD], g_xl[NTD];
__device__ bf16  g_wqh[WSZ], g_wql[WSZ], g_wkh[WSZ], g_wkl[WSZ], g_wvh[WSZ], g_wvl[WSZ];
__device__ float g_qf[NTD], g_kf[NTD], g_vf[NTD];
__device__ bf16  g_qh[NTD], g_ql[NTD], g_kh[NTD], g_kl[NTD], g_vh[NTD], g_vl[NTD];
__device__ bf16  g_vth[NTD], g_vtl[NTD];    // V transposed: [b][dim][seq]
__device__ float g_s[SSZ];                  // scores fp32
__device__ bf16  g_ph[SSZ], g_pl[SSZ];      // softmax probs hi/lo

__device__ __forceinline__ uint32_t smem_u32(const void* p) {
    uint32_t a;
    asm("{ .reg .u64 t; cvta.to.shared.u64 t, %1; cvt.u32.u64 %0, t; }" : "=r"(a) : "l"(p));
    return a;
}

// ---------------------------------------------------------------------------
// NT GEMM via wmma (HMMA), 3-pass bf16 hi/lo split:
//   C[M,N] = alpha * ( Ah*Bh^T + Ah*Bl^T + Al*Bh^T )
// A*: [M,K] K-major (lda), B*: [N,K] K-major (ldb), C fp32 [M,N] (ldc).
// CTA tile 128x128, BK=32, 256 threads (8 warps, 2x4, warp tile 64x32).
// Double-buffered smem via cp.async.
// Requires M%128==0, N%128==0, K%32==0.
// ---------------------------------------------------------------------------
#define BM 128
#define BN 128
#define BK 32
#define LDS 40   // 32 + 8 pad (bf16 elems): 80B row stride, 16B-aligned chunks

__global__ __launch_bounds__(256) void gemm_wmma(
    const bf16* __restrict__ Ah, const bf16* __restrict__ Al,
    const bf16* __restrict__ Bh, const bf16* __restrict__ Bl,
    float* __restrict__ C,
    int K, int lda, int ldb, int ldc, float alpha,
    size_t sA, size_t sB, size_t sC)
{
    __shared__ bf16 As[2][BM][LDS];
    __shared__ bf16 Bs[2][BN][LDS];

    const int tid = threadIdx.x;
    const int wid = tid >> 5;
    const int m0 = blockIdx.x * BM;
    const int n0 = blockIdx.y * BN;
    const int z  = blockIdx.z;
    Ah += (size_t)z * sA; Al += (size_t)z * sA;
    Bh += (size_t)z * sB; Bl += (size_t)z * sB;
    C  += (size_t)z * sC;

    const int NCP = K / BK;       // chunks per pass
    const int NT  = 3 * NCP;      // hi*hi, hi*lo, lo*hi

    const int wm = (wid >> 2) * 64;   // warp M offset
    const int wn = (wid & 3) * 32;    // warp N offset

    wmma::fragment<wmma::accumulator, 16, 16, 16, float> acc[4][2];
#pragma unroll
    for (int i = 0; i < 4; i++)
#pragma unroll
        for (int j = 0; j < 2; j++) wmma::fill_fragment(acc[i][j], 0.0f);

    auto load_stage = [&](int s, int kt) {
        const int p  = kt / NCP;
        const int kc = (kt - p * NCP) * BK;
        const bf16* A = (p < 2) ? Ah : Al;
        const bf16* B = (p == 1) ? Bl : Bh;
#pragma unroll
        for (int h = 0; h < 2; h++) {
            const int c   = tid + h * 256;       // chunk id 0..511
            const int r   = c >> 2;              // row 0..127
            const int col = (c & 3) * 8;         // bf16 col offset (16B chunks)
            const bf16* ga = A + (size_t)(m0 + r) * lda + kc + col;
            uint32_t da = smem_u32(&As[s][r][col]);
            asm volatile("cp.async.cg.shared.global [%0], [%1], 16;" :: "r"(da), "l"(ga));
            const bf16* gb = B + (size_t)(n0 + r) * ldb + kc + col;
            uint32_t db = smem_u32(&Bs[s][r][col]);
            asm volatile("cp.async.cg.shared.global [%0], [%1], 16;" :: "r"(db), "l"(gb));
        }
        asm volatile("cp.async.commit_group;" ::: "memory");
    };

    load_stage(0, 0);

    for (int kt = 0; kt < NT; kt++) {
        const int cur = kt & 1;
        asm volatile("cp.async.wait_group 0;" ::: "memory");
        __syncthreads();
        if (kt + 1 < NT) load_stage(cur ^ 1, kt + 1);

#pragma unroll
        for (int kk = 0; kk < BK; kk += 16) {
            wmma::fragment<wmma::matrix_a, 16, 16, 16, bf16, wmma::row_major> fa[4];
            wmma::fragment<wmma::matrix_b, 16, 16, 16, bf16, wmma::col_major> fb[2];
#pragma unroll
            for (int i = 0; i < 4; i++)
                wmma::load_matrix_sync(fa[i], &As[cur][wm + 16 * i][kk], LDS);
#pragma unroll
            for (int j = 0; j < 2; j++)
                wmma::load_matrix_sync(fb[j], &Bs[cur][wn + 16 * j][kk], LDS);
#pragma unroll
            for (int i = 0; i < 4; i++)
#pragma unroll
                for (int j = 0; j < 2; j++)
                    wmma::mma_sync(acc[i][j], fa[i], fb[j], acc[i][j]);
        }
        __syncthreads();
    }

#pragma unroll
    for (int i = 0; i < 4; i++)
#pragma unroll
        for (int j = 0; j < 2; j++) {
#pragma unroll
            for (int t = 0; t < acc[i][j].num_elements; t++) acc[i][j].x[t] *= alpha;
            float* cp = C + (size_t)(m0 + wm + 16 * i) * ldc + (n0 + wn + 16 * j);
            wmma::store_matrix_sync(cp, acc[i][j], ldc, wmma::mem_row_major);
        }
}

// ---------------- fp32 -> bf16 hi/lo split (no bias) ----------------
__global__ __launch_bounds__(256) void split_k(const float* __restrict__ in,
                                               bf16* __restrict__ h, bf16* __restrict__ l,
                                               int n4)
{
    int i = blockIdx.x * blockDim.x + threadIdx.x;
    if (i >= n4) return;
    float4 v = ((const float4*)in)[i];
    float vv[4] = {v.x, v.y, v.z, v.w};
    union { unsigned short u[4]; uint2 q; } hh, ll;
#pragma unroll
    for (int e = 0; e < 4; e++) {
        bf16 hb = __float2bfloat16(vv[e]);
        bf16 lb = __float2bfloat16(vv[e] - __bfloat162float(hb));
        hh.u[e] = *(unsigned short*)&hb;
        ll.u[e] = *(unsigned short*)&lb;
    }
    ((uint2*)h)[i] = hh.q;
    ((uint2*)l)[i] = ll.q;
}

// ---------------- fp32 + bias -> bf16 hi/lo split ----------------
__global__ __launch_bounds__(256) void bias_split_k(const float* __restrict__ in,
                                                    const float* __restrict__ bias,
                                                    bf16* __restrict__ h, bf16* __restrict__ l,
                                                    int n4)
{
    int i = blockIdx.x * blockDim.x + threadIdx.x;
    if (i >= n4) return;
    float4 v = ((const float4*)in)[i];
    const int col = (i * 4) % DIM;
    float4 bb = *(const float4*)(bias + col);
    float vv[4] = {v.x + bb.x, v.y + bb.y, v.z + bb.z, v.w + bb.w};
    union { unsigned short u[4]; uint2 q; } hh, ll;
#pragma unroll
    for (int e = 0; e < 4; e++) {
        bf16 hb = __float2bfloat16(vv[e]);
        bf16 lb = __float2bfloat16(vv[e] - __bfloat162float(hb));
        hh.u[e] = *(unsigned short*)&hb;
        ll.u[e] = *(unsigned short*)&lb;
    }
    ((uint2*)h)[i] = hh.q;
    ((uint2*)l)[i] = ll.q;
}

// ---------------- transpose V[b][s][d] -> Vt[b][d][s] (hi & lo) ----------------
__global__ void transpose_k(const bf16* __restrict__ vh, const bf16* __restrict__ vl,
                            bf16* __restrict__ th, bf16* __restrict__ tl)
{
    __shared__ bf16 sh[32][33], sl[32][33];
    const int z = blockIdx.z;
    const size_t ib = (size_t)z * SEQ * DIM;
    const int d0 = blockIdx.x * 32, s0 = blockIdx.y * 32;
    const int tx = threadIdx.x, ty = threadIdx.y;
#pragma unroll
    for (int i = 0; i < 32; i += 8) {
        sh[ty + i][tx] = vh[ib + (size_t)(s0 + ty + i) * DIM + d0 + tx];
        sl[ty + i][tx] = vl[ib + (size_t)(s0 + ty + i) * DIM + d0 + tx];
    }
    __syncthreads();
#pragma unroll
    for (int i = 0; i < 32; i += 8) {
        th[ib + (size_t)(d0 + ty + i) * SEQ + s0 + tx] = sh[tx][ty + i];
        tl[ib + (size_t)(d0 + ty + i) * SEQ + s0 + tx] = sl[tx][ty + i];
    }
}

// ---------------- softmax: fp32 scores row -> P hi/lo bf16 ----------------
__global__ __launch_bounds__(256) void softmax_k(const float* __restrict__ S,
                                                 bf16* __restrict__ ph, bf16* __restrict__ pl)
{
    const size_t rb = (size_t)blockIdx.x * SEQ;
    const float* p = S + rb;
    const int tid = threadIdx.x;

    float4 v[4];
#pragma unroll
    for (int i = 0; i < 4; i++) v[i] = *(const float4*)(p + tid * 4 + i * 1024);

    float m = -INFINITY;
#pragma unroll
    for (int i = 0; i < 4; i++)
        m = fmaxf(m, fmaxf(fmaxf(v[i].x, v[i].y), fmaxf(v[i].z, v[i].w)));

    __shared__ float red[256];
    red[tid] = m; __syncthreads();
#pragma unroll
    for (int s = 128; s > 0; s >>= 1) {
        if (tid < s) red[tid] = fmaxf(red[tid], red[tid + s]);
        __syncthreads();
    }
    m = red[0]; __syncthreads();

    float sum = 0.0f;
#pragma unroll
    for (int i = 0; i < 4; i++) {
        v[i].x = __expf(v[i].x - m); v[i].y = __expf(v[i].y - m);
        v[i].z = __expf(v[i].z - m); v[i].w = __expf(v[i].w - m);
        sum += v[i].x + v[i].y + v[i].z + v[i].w;
    }
    red[tid] = sum; __syncthreads();
#pragma unroll
    for (int s = 128; s > 0; s >>= 1) {
        if (tid < s) red[tid] += red[tid + s];
        __syncthreads();
    }
    const float inv = 1.0f / red[0];

#pragma unroll
    for (int i = 0; i < 4; i++) {
        float vv[4] = {v[i].x * inv, v[i].y * inv, v[i].z * inv, v[i].w * inv};
        union { unsigned short u[4]; uint2 q; } hh, ll;
#pragma unroll
        for (int e = 0; e < 4; e++) {
            bf16 hb = __float2bfloat16(vv[e]);
            bf16 lb = __float2bfloat16(vv[e] - __bfloat162float(hb));
            hh.u[e] = *(unsigned short*)&hb;
            ll.u[e] = *(unsigned short*)&lb;
        }
        *(uint2*)(ph + rb + tid * 4 + i * 1024) = hh.q;
        *(uint2*)(pl + rb + tid * 4 + i * 1024) = ll.q;
    }
}

// ---------------- launch ----------------
extern "C" void kernel_launch(void* const* d_in, const int* in_sizes, int n_in,
                              void* d_out, int out_size)
{
    const float* x  = (const float*)d_in[0];
    const float* Wq = (const float*)d_in[1];
    const float* bq = (const float*)d_in[2];
    const float* Wk = (const float*)d_in[3];
    const float* bk = (const float*)d_in[4];
    const float* Wv = (const float*)d_in[5];
    const float* bv = (const float*)d_in[6];
    float* out = (float*)d_out;

    bf16 *xh, *xl, *wqh, *wql, *wkh, *wkl, *wvh, *wvl;
    bf16 *qh, *ql, *kh, *kl, *vh, *vl, *vth, *vtl, *pph, *ppl;
    float *qf, *kf, *vf, *sc;
    cudaGetSymbolAddress((void**)&xh, g_xh);   cudaGetSymbolAddress((void**)&xl, g_xl);
    cudaGetSymbolAddress((void**)&wqh, g_wqh); cudaGetSymbolAddress((void**)&wql, g_wql);
    cudaGetSymbolAddress((void**)&wkh, g_wkh); cudaGetSymbolAddress((void**)&wkl, g_wkl);
    cudaGetSymbolAddress((void**)&wvh, g_wvh); cudaGetSymbolAddress((void**)&wvl, g_wvl);
    cudaGetSymbolAddress((void**)&qf, g_qf);   cudaGetSymbolAddress((void**)&kf, g_kf);
    cudaGetSymbolAddress((void**)&vf, g_vf);
    cudaGetSymbolAddress((void**)&qh, g_qh);   cudaGetSymbolAddress((void**)&ql, g_ql);
    cudaGetSymbolAddress((void**)&kh, g_kh);   cudaGetSymbolAddress((void**)&kl, g_kl);
    cudaGetSymbolAddress((void**)&vh, g_vh);   cudaGetSymbolAddress((void**)&vl, g_vl);
    cudaGetSymbolAddress((void**)&vth, g_vth); cudaGetSymbolAddress((void**)&vtl, g_vtl);
    cudaGetSymbolAddress((void**)&pph, g_ph);  cudaGetSymbolAddress((void**)&ppl, g_pl);
    cudaGetSymbolAddress((void**)&sc, g_s);

    const float scale = 1.0f / sqrtf((float)DIM);

    // 1. split inputs to bf16 hi/lo
    split_k<<<(int)(NTD / 4 + 255) / 256, 256>>>(x, xh, xl, (int)(NTD / 4));
    split_k<<<(int)(WSZ / 4 + 255) / 256, 256>>>(Wq, wqh, wql, (int)(WSZ / 4));
    split_k<<<(int)(WSZ / 4 + 255) / 256, 256>>>(Wk, wkh, wkl, (int)(WSZ / 4));
    split_k<<<(int)(WSZ / 4 + 255) / 256, 256>>>(Wv, wvh, wvl, (int)(WSZ / 4));

    // 2. projections: [16384,768] = x * W^T  (fp32 out)
    dim3 gp(NTOK / BM, DIM / BN, 1);
    gemm_wmma<<<gp, 256>>>(xh, xl, wqh, wql, qf, DIM, DIM, DIM, DIM, 1.0f, 0, 0, 0);
    gemm_wmma<<<gp, 256>>>(xh, xl, wkh, wkl, kf, DIM, DIM, DIM, DIM, 1.0f, 0, 0, 0);
    gemm_wmma<<<gp, 256>>>(xh, xl, wvh, wvl, vf, DIM, DIM, DIM, DIM, 1.0f, 0, 0, 0);

    // 3. bias + split to bf16 hi/lo
    bias_split_k<<<(int)(NTD / 4 + 255) / 256, 256>>>(qf, bq, qh, ql, (int)(NTD / 4));
    bias_split_k<<<(int)(NTD / 4 + 255) / 256, 256>>>(kf, bk, kh, kl, (int)(NTD / 4));
    bias_split_k<<<(int)(NTD / 4 + 255) / 256, 256>>>(vf, bv, vh, vl, (int)(NTD / 4));

    // 4. transpose V -> Vt[b][d][s]
    transpose_k<<<dim3(DIM / 32, SEQ / 32, BATCH), dim3(32, 8)>>>(vh, vl, vth, vtl);

    // 5. scores[b] = scale * Q[b] K[b]^T
    gemm_wmma<<<dim3(SEQ / BM, SEQ / BN, BATCH), 256>>>(
        qh, ql, kh, kl, sc, DIM, DIM, DIM, SEQ, scale,
        (size_t)SEQ * DIM, (size_t)SEQ * DIM, (size_t)SEQ * SEQ);

    // 6. softmax rows -> P hi/lo
    softmax_k<<<NTOK, 256>>>(sc, pph, ppl);

    // 7. out[b] = P[b] V[b]   (B operand = Vt, K-major over seq)
    gemm_wmma<<<dim3(SEQ / BM, DIM / BN, BATCH), 256>>>(
        pph, ppl, vth, vtl, out, SEQ, SEQ, SEQ, DIM, 1.0f,
        (size_t)SEQ * SEQ, (size_t)SEQ * DIM, (size_t)SEQ * DIM);

    (void)in_sizes; (void)n_in; (void)out_size;
}

// round 6
// speedup vs baseline: 2.0014x; 1.0934x over previous
#include <cuda_runtime.h>
#include <cuda_bf16.h>
#include <mma.h>
#include <cstdint>
#include <math.h>

using namespace nvcuda;
using bf16 = __nv_bfloat16;

#define BATCH 4
#define SEQ   4096
#define DIM   768
#define NTOK  (BATCH * SEQ)                 // 16384
#define NTD   ((size_t)NTOK * DIM)
#define WSZ   ((size_t)DIM * DIM)
#define SSZ   ((size_t)BATCH * SEQ * SEQ)

// ---------------- device scratch (allocation-free rule) ----------------
__device__ bf16  g_xh[NTD], g_xl[NTD];
__device__ bf16  g_wqh[WSZ], g_wql[WSZ], g_wkh[WSZ], g_wkl[WSZ], g_wvh[WSZ], g_wvl[WSZ];
__device__ float g_qf[NTD], g_kf[NTD], g_vf[NTD];
__device__ bf16  g_qh[NTD], g_ql[NTD], g_kh[NTD], g_kl[NTD], g_vh[NTD], g_vl[NTD];
__device__ bf16  g_vth[NTD], g_vtl[NTD];    // V transposed: [b][dim][seq]
__device__ float g_s[SSZ];                  // scores fp32
__device__ bf16  g_ph[SSZ], g_pl[SSZ];      // softmax probs hi/lo

__device__ __forceinline__ uint32_t smem_u32(const void* p) {
    uint32_t a;
    asm("{ .reg .u64 t; cvta.to.shared.u64 t, %1; cvt.u32.u64 %0, t; }" : "=r"(a) : "l"(p));
    return a;
}

// ---------------------------------------------------------------------------
// NT GEMM via wmma (HMMA), 3-pass bf16 hi/lo split:
//   C[M,N] = alpha * ( Ah*Bh^T + Ah*Bl^T + Al*Bh^T )
// CTA tile 128x256, BK=64, 256 threads (8 warps 2x4, warp tile 64x64).
// 3-stage cp.async pipeline, dynamic smem, pad-8 rows.
// Requires M%128==0, N%256==0, K%64==0.
// ---------------------------------------------------------------------------
#define BM 128
#define BN 256
#define BK 64
#define LDSK (BK + 8)                          // 72 elems; 144B row (16B mult)
#define A_BYTES (BM * LDSK * 2)                // 18432
#define B_BYTES (BN * LDSK * 2)                // 36864
#define STAGE_BYTES (A_BYTES + B_BYTES)        // 55296
#define NSTAGE 3
#define GEMM_SMEM (NSTAGE * STAGE_BYTES)       // 165888

__global__ __launch_bounds__(256, 1) void gemm_wmma(
    const bf16* __restrict__ Ah, const bf16* __restrict__ Al,
    const bf16* __restrict__ Bh, const bf16* __restrict__ Bl,
    float* __restrict__ C,
    int K, int lda, int ldb, int ldc, float alpha,
    size_t sA, size_t sB, size_t sC)
{
    extern __shared__ char smem[];

    const int tid = threadIdx.x;
    const int wid = tid >> 5;
    const int m0 = blockIdx.x * BM;
    const int n0 = blockIdx.y * BN;
    const int z  = blockIdx.z;
    Ah += (size_t)z * sA; Al += (size_t)z * sA;
    Bh += (size_t)z * sB; Bl += (size_t)z * sB;
    C  += (size_t)z * sC;

    const int NCP = K / BK;       // chunks per pass
    const int NT  = 3 * NCP;      // hi*hi, hi*lo, lo*hi

    const int wm = (wid >> 2) * 64;   // warp M offset
    const int wn = (wid & 3) * 64;    // warp N offset

    wmma::fragment<wmma::accumulator, 16, 16, 16, float> acc[4][4];
#pragma unroll
    for (int i = 0; i < 4; i++)
#pragma unroll
        for (int j = 0; j < 4; j++) wmma::fill_fragment(acc[i][j], 0.0f);

    auto load_stage = [&](int s, int kt) {
        const int p  = kt / NCP;
        const int kc = (kt - p * NCP) * BK;
        const bf16* A = (p < 2) ? Ah : Al;
        const bf16* B = (p == 1) ? Bl : Bh;
        bf16* As = (bf16*)(smem + s * STAGE_BYTES);
        bf16* Bs = (bf16*)(smem + s * STAGE_BYTES + A_BYTES);
        // A: 128 rows x 64 cols = 1024 16B chunks
#pragma unroll
        for (int h = 0; h < 4; h++) {
            const int c   = tid + h * 256;
            const int r   = c >> 3;
            const int col = (c & 7) * 8;
            uint32_t da = smem_u32(As + r * LDSK + col);
            const bf16* ga = A + (size_t)(m0 + r) * lda + kc + col;
            asm volatile("cp.async.cg.shared.global [%0], [%1], 16;" :: "r"(da), "l"(ga));
        }
        // B: 256 rows x 64 cols = 2048 16B chunks
#pragma unroll
        for (int h = 0; h < 8; h++) {
            const int c   = tid + h * 256;
            const int r   = c >> 3;
            const int col = (c & 7) * 8;
            uint32_t db = smem_u32(Bs + r * LDSK + col);
            const bf16* gb = B + (size_t)(n0 + r) * ldb + kc + col;
            asm volatile("cp.async.cg.shared.global [%0], [%1], 16;" :: "r"(db), "l"(gb));
        }
        asm volatile("cp.async.commit_group;" ::: "memory");
    };

    // Prologue: fill stages 0..NSTAGE-2
#pragma unroll
    for (int s = 0; s < NSTAGE - 1; s++) load_stage(s, s);

    for (int kt = 0; kt < NT; kt++) {
        const int cur = kt % NSTAGE;
        asm volatile("cp.async.wait_group %0;" :: "n"(NSTAGE - 2) : "memory");
        __syncthreads();
        if (kt + NSTAGE - 1 < NT) load_stage((kt + NSTAGE - 1) % NSTAGE, kt + NSTAGE - 1);

        const bf16* As = (const bf16*)(smem + cur * STAGE_BYTES);
        const bf16* Bs = (const bf16*)(smem + cur * STAGE_BYTES + A_BYTES);
#pragma unroll
        for (int kk = 0; kk < BK; kk += 16) {
            wmma::fragment<wmma::matrix_a, 16, 16, 16, bf16, wmma::row_major> fa[4];
#pragma unroll
            for (int i = 0; i < 4; i++)
                wmma::load_matrix_sync(fa[i], As + (wm + 16 * i) * LDSK + kk, LDSK);
#pragma unroll
            for (int j = 0; j < 4; j++) {
                wmma::fragment<wmma::matrix_b, 16, 16, 16, bf16, wmma::col_major> fb;
                wmma::load_matrix_sync(fb, Bs + (wn + 16 * j) * LDSK + kk, LDSK);
#pragma unroll
                for (int i = 0; i < 4; i++)
                    wmma::mma_sync(acc[i][j], fa[i], fb, acc[i][j]);
            }
        }
    }

#pragma unroll
    for (int i = 0; i < 4; i++)
#pragma unroll
        for (int j = 0; j < 4; j++) {
#pragma unroll
            for (int t = 0; t < acc[i][j].num_elements; t++) acc[i][j].x[t] *= alpha;
            float* cp = C + (size_t)(m0 + wm + 16 * i) * ldc + (n0 + wn + 16 * j);
            wmma::store_matrix_sync(cp, acc[i][j], ldc, wmma::mem_row_major);
        }
}

// ---------------- fp32 -> bf16 hi/lo split (no bias) ----------------
__global__ __launch_bounds__(256) void split_k(const float* __restrict__ in,
                                               bf16* __restrict__ h, bf16* __restrict__ l,
                                               int n4)
{
    int i = blockIdx.x * blockDim.x + threadIdx.x;
    if (i >= n4) return;
    float4 v = ((const float4*)in)[i];
    float vv[4] = {v.x, v.y, v.z, v.w};
    union { unsigned short u[4]; uint2 q; } hh, ll;
#pragma unroll
    for (int e = 0; e < 4; e++) {
        bf16 hb = __float2bfloat16(vv[e]);
        bf16 lb = __float2bfloat16(vv[e] - __bfloat162float(hb));
        hh.u[e] = *(unsigned short*)&hb;
        ll.u[e] = *(unsigned short*)&lb;
    }
    ((uint2*)h)[i] = hh.q;
    ((uint2*)l)[i] = ll.q;
}

// ---------------- fp32 + bias -> bf16 hi/lo split ----------------
__global__ __launch_bounds__(256) void bias_split_k(const float* __restrict__ in,
                                                    const float* __restrict__ bias,
                                                    bf16* __restrict__ h, bf16* __restrict__ l,
                                                    int n4)
{
    int i = blockIdx.x * blockDim.x + threadIdx.x;
    if (i >= n4) return;
    float4 v = ((const float4*)in)[i];
    const int col = (i * 4) % DIM;
    float4 bb = *(const float4*)(bias + col);
    float vv[4] = {v.x + bb.x, v.y + bb.y, v.z + bb.z, v.w + bb.w};
    union { unsigned short u[4]; uint2 q; } hh, ll;
#pragma unroll
    for (int e = 0; e < 4; e++) {
        bf16 hb = __float2bfloat16(vv[e]);
        bf16 lb = __float2bfloat16(vv[e] - __bfloat162float(hb));
        hh.u[e] = *(unsigned short*)&hb;
        ll.u[e] = *(unsigned short*)&lb;
    }
    ((uint2*)h)[i] = hh.q;
    ((uint2*)l)[i] = ll.q;
}

// ---------------- transpose V[b][s][d] -> Vt[b][d][s] (hi & lo) ----------------
__global__ void transpose_k(const bf16* __restrict__ vh, const bf16* __restrict__ vl,
                            bf16* __restrict__ th, bf16* __restrict__ tl)
{
    __shared__ bf16 sh[32][33], sl[32][33];
    const int z = blockIdx.z;
    const size_t ib = (size_t)z * SEQ * DIM;
    const int d0 = blockIdx.x * 32, s0 = blockIdx.y * 32;
    const int tx = threadIdx.x, ty = threadIdx.y;
#pragma unroll
    for (int i = 0; i < 32; i += 8) {
        sh[ty + i][tx] = vh[ib + (size_t)(s0 + ty + i) * DIM + d0 + tx];
        sl[ty + i][tx] = vl[ib + (size_t)(s0 + ty + i) * DIM + d0 + tx];
    }
    __syncthreads();
#pragma unroll
    for (int i = 0; i < 32; i += 8) {
        th[ib + (size_t)(d0 + ty + i) * SEQ + s0 + tx] = sh[tx][ty + i];
        tl[ib + (size_t)(d0 + ty + i) * SEQ + s0 + tx] = sl[tx][ty + i];
    }
}

// ---------------- softmax: fp32 scores row -> P hi/lo bf16 ----------------
__global__ __launch_bounds__(256) void softmax_k(const float* __restrict__ S,
                                                 bf16* __restrict__ ph, bf16* __restrict__ pl)
{
    const size_t rb = (size_t)blockIdx.x * SEQ;
    const float* p = S + rb;
    const int tid = threadIdx.x;

    float4 v[4];
#pragma unroll
    for (int i = 0; i < 4; i++) v[i] = *(const float4*)(p + tid * 4 + i * 1024);

    float m = -INFINITY;
#pragma unroll
    for (int i = 0; i < 4; i++)
        m = fmaxf(m, fmaxf(fmaxf(v[i].x, v[i].y), fmaxf(v[i].z, v[i].w)));

    __shared__ float red[256];
    red[tid] = m; __syncthreads();
#pragma unroll
    for (int s = 128; s > 0; s >>= 1) {
        if (tid < s) red[tid] = fmaxf(red[tid], red[tid + s]);
        __syncthreads();
    }
    m = red[0]; __syncthreads();

    float sum = 0.0f;
#pragma unroll
    for (int i = 0; i < 4; i++) {
        v[i].x = __expf(v[i].x - m); v[i].y = __expf(v[i].y - m);
        v[i].z = __expf(v[i].z - m); v[i].w = __expf(v[i].w - m);
        sum += v[i].x + v[i].y + v[i].z + v[i].w;
    }
    red[tid] = sum; __syncthreads();
#pragma unroll
    for (int s = 128; s > 0; s >>= 1) {
        if (tid < s) red[tid] += red[tid + s];
        __syncthreads();
    }
    const float inv = 1.0f / red[0];

#pragma unroll
    for (int i = 0; i < 4; i++) {
        float vv[4] = {v[i].x * inv, v[i].y * inv, v[i].z * inv, v[i].w * inv};
        union { unsigned short u[4]; uint2 q; } hh, ll;
#pragma unroll
        for (int e = 0; e < 4; e++) {
            bf16 hb = __float2bfloat16(vv[e]);
            bf16 lb = __float2bfloat16(vv[e] - __bfloat162float(hb));
            hh.u[e] = *(unsigned short*)&hb;
            ll.u[e] = *(unsigned short*)&lb;
        }
        *(uint2*)(ph + rb + tid * 4 + i * 1024) = hh.q;
        *(uint2*)(pl + rb + tid * 4 + i * 1024) = ll.q;
    }
}

// ---------------- launch ----------------
extern "C" void kernel_launch(void* const* d_in, const int* in_sizes, int n_in,
                              void* d_out, int out_size)
{
    const float* x  = (const float*)d_in[0];
    const float* Wq = (const float*)d_in[1];
    const float* bq = (const float*)d_in[2];
    const float* Wk = (const float*)d_in[3];
    const float* bk = (const float*)d_in[4];
    const float* Wv = (const float*)d_in[5];
    const float* bv = (const float*)d_in[6];
    float* out = (float*)d_out;

    bf16 *xh, *xl, *wqh, *wql, *wkh, *wkl, *wvh, *wvl;
    bf16 *qh, *ql, *kh, *kl, *vh, *vl, *vth, *vtl, *pph, *ppl;
    float *qf, *kf, *vf, *sc;
    cudaGetSymbolAddress((void**)&xh, g_xh);   cudaGetSymbolAddress((void**)&xl, g_xl);
    cudaGetSymbolAddress((void**)&wqh, g_wqh); cudaGetSymbolAddress((void**)&wql, g_wql);
    cudaGetSymbolAddress((void**)&wkh, g_wkh); cudaGetSymbolAddress((void**)&wkl, g_wkl);
    cudaGetSymbolAddress((void**)&wvh, g_wvh); cudaGetSymbolAddress((void**)&wvl, g_wvl);
    cudaGetSymbolAddress((void**)&qf, g_qf);   cudaGetSymbolAddress((void**)&kf, g_kf);
    cudaGetSymbolAddress((void**)&vf, g_vf);
    cudaGetSymbolAddress((void**)&qh, g_qh);   cudaGetSymbolAddress((void**)&ql, g_ql);
    cudaGetSymbolAddress((void**)&kh, g_kh);   cudaGetSymbolAddress((void**)&kl, g_kl);
    cudaGetSymbolAddress((void**)&vh, g_vh);   cudaGetSymbolAddress((void**)&vl, g_vl);
    cudaGetSymbolAddress((void**)&vth, g_vth); cudaGetSymbolAddress((void**)&vtl, g_vtl);
    cudaGetSymbolAddress((void**)&pph, g_ph);  cudaGetSymbolAddress((void**)&ppl, g_pl);
    cudaGetSymbolAddress((void**)&sc, g_s);

    cudaFuncSetAttribute(gemm_wmma, cudaFuncAttributeMaxDynamicSharedMemorySize, GEMM_SMEM);

    const float scale = 1.0f / sqrtf((float)DIM);

    // 1. split inputs to bf16 hi/lo
    split_k<<<(int)(NTD / 4 + 255) / 256, 256>>>(x, xh, xl, (int)(NTD / 4));
    split_k<<<(int)(WSZ / 4 + 255) / 256, 256>>>(Wq, wqh, wql, (int)(WSZ / 4));
    split_k<<<(int)(WSZ / 4 + 255) / 256, 256>>>(Wk, wkh, wkl, (int)(WSZ / 4));
    split_k<<<(int)(WSZ / 4 + 255) / 256, 256>>>(Wv, wvh, wvl, (int)(WSZ / 4));

    // 2. projections: [16384,768] = x * W^T  (fp32 out)
    dim3 gp(NTOK / BM, DIM / BN, 1);
    gemm_wmma<<<gp, 256, GEMM_SMEM>>>(xh, xl, wqh, wql, qf, DIM, DIM, DIM, DIM, 1.0f, 0, 0, 0);
    gemm_wmma<<<gp, 256, GEMM_SMEM>>>(xh, xl, wkh, wkl, kf, DIM, DIM, DIM, DIM, 1.0f, 0, 0, 0);
    gemm_wmma<<<gp, 256, GEMM_SMEM>>>(xh, xl, wvh, wvl, vf, DIM, DIM, DIM, DIM, 1.0f, 0, 0, 0);

    // 3. bias + split to bf16 hi/lo
    bias_split_k<<<(int)(NTD / 4 + 255) / 256, 256>>>(qf, bq, qh, ql, (int)(NTD / 4));
    bias_split_k<<<(int)(NTD / 4 + 255) / 256, 256>>>(kf, bk, kh, kl, (int)(NTD / 4));
    bias_split_k<<<(int)(NTD / 4 + 255) / 256, 256>>>(vf, bv, vh, vl, (int)(NTD / 4));

    // 4. transpose V -> Vt[b][d][s]
    transpose_k<<<dim3(DIM / 32, SEQ / 32, BATCH), dim3(32, 8)>>>(vh, vl, vth, vtl);

    // 5. scores[b] = scale * Q[b] K[b]^T
    gemm_wmma<<<dim3(SEQ / BM, SEQ / BN, BATCH), 256, GEMM_SMEM>>>(
        qh, ql, kh, kl, sc, DIM, DIM, DIM, SEQ, scale,
        (size_t)SEQ * DIM, (size_t)SEQ * DIM, (size_t)SEQ * SEQ);

    // 6. softmax rows -> P hi/lo
    softmax_k<<<NTOK, 256>>>(sc, pph, ppl);

    // 7. out[b] = P[b] V[b]   (B operand = Vt, K-major over seq)
    gemm_wmma<<<dim3(SEQ / BM, DIM / BN, BATCH), 256, GEMM_SMEM>>>(
        pph, ppl, vth, vtl, out, SEQ, SEQ, SEQ, DIM, 1.0f,
        (size_t)SEQ * SEQ, (size_t)SEQ * DIM, (size_t)SEQ * DIM);

    (void)in_sizes; (void)n_in; (void)out_size;
}

// round 8
// speedup vs baseline: 2.5920x; 1.2951x over previous
#include <cuda_runtime.h>
#include <cuda_bf16.h>
#include <cstdint>
#include <math.h>

using bf16 = __nv_bfloat16;

#define BATCH 4
#define SEQ   4096
#define DIM   768
#define NTOK  (BATCH * SEQ)                 // 16384
#define NTD   ((size_t)NTOK * DIM)
#define WSZ   ((size_t)DIM * DIM)
#define SSZ   ((size_t)BATCH * SEQ * SEQ)

// ---------------- device scratch (allocation-free rule) ----------------
__device__ bf16  g_xh[NTD], g_xl[NTD];
__device__ bf16  g_wqh[WSZ], g_wql[WSZ], g_wkh[WSZ], g_wkl[WSZ], g_wvh[WSZ], g_wvl[WSZ];
__device__ float g_qf[NTD], g_kf[NTD], g_vf[NTD];
__device__ bf16  g_qh[NTD], g_ql[NTD], g_kh[NTD], g_kl[NTD], g_vh[NTD], g_vl[NTD];
__device__ bf16  g_vth[NTD], g_vtl[NTD];    // V transposed: [b][dim][seq]
__device__ float g_s[SSZ];                  // scores fp32
__device__ bf16  g_ph[SSZ], g_pl[SSZ];      // softmax probs hi/lo

__device__ __forceinline__ uint32_t smem_u32(const void* p) {
    uint32_t a;
    asm("{ .reg .u64 t; cvta.to.shared.u64 t, %1; cvt.u32.u64 %0, t; }" : "=r"(a) : "l"(p));
    return a;
}

__device__ __forceinline__ void ldsm4(uint32_t* r, uint32_t addr) {
    asm volatile("ldmatrix.sync.aligned.m8n8.x4.shared.b16 {%0,%1,%2,%3}, [%4];"
                 : "=r"(r[0]), "=r"(r[1]), "=r"(r[2]), "=r"(r[3]) : "r"(addr));
}
__device__ __forceinline__ void mma16816(float* d, const uint32_t* a, const uint32_t* b) {
    asm volatile("mma.sync.aligned.m16n8k16.row.col.f32.bf16.bf16.f32 "
                 "{%0,%1,%2,%3}, {%4,%5,%6,%7}, {%8,%9}, {%0,%1,%2,%3};"
                 : "+f"(d[0]), "+f"(d[1]), "+f"(d[2]), "+f"(d[3])
                 : "r"(a[0]), "r"(a[1]), "r"(a[2]), "r"(a[3]), "r"(b[0]), "r"(b[1]));
}

// ---------------------------------------------------------------------------
// NT GEMM via raw mma.sync + ldmatrix, 3-pass bf16 hi/lo split:
//   C[M,N] = alpha * ( Ah*Bh^T + Ah*Bl^T + Al*Bh^T )
// CTA tile 128x256, BK=64, 256 threads (8 warps 2x4, warp tile 64x64).
// 3-stage cp.async pipeline; smem rows 128B with XOR-16B swizzle.
// Requires M%128==0, N%256==0, K%64==0.
// ---------------------------------------------------------------------------
#define BM 128
#define BN 256
#define BK 64
#define A_BYTES (BM * 128)                 // 16384
#define B_BYTES (BN * 128)                 // 32768
#define STAGE_BYTES (A_BYTES + B_BYTES)    // 49152
#define NSTAGE 3
#define GEMM_SMEM (NSTAGE * STAGE_BYTES)   // 147456

__global__ __launch_bounds__(256, 1) void gemm_mma(
    const bf16* __restrict__ Ah, const bf16* __restrict__ Al,
    const bf16* __restrict__ Bh, const bf16* __restrict__ Bl,
    float* __restrict__ C,
    int K, int lda, int ldb, int ldc, float alpha,
    size_t sA, size_t sB, size_t sC)
{
    extern __shared__ char smem[];
    const uint32_t sbase = smem_u32(smem);

    const int tid = threadIdx.x;
    const int wid = tid >> 5;
    const int l   = tid & 31;
    const int m0 = blockIdx.x * BM;
    const int n0 = blockIdx.y * BN;
    const int z  = blockIdx.z;
    Ah += (size_t)z * sA; Al += (size_t)z * sA;
    Bh += (size_t)z * sB; Bl += (size_t)z * sB;
    C  += (size_t)z * sC;

    const int NCP = K / BK;
    const int NT  = 3 * NCP;      // hi*hi, hi*lo, lo*hi

    const int wm = (wid >> 2) * 64;   // warp M offset in CTA tile
    const int wn = (wid & 3) * 64;    // warp N offset

    float acc[4][8][4];
#pragma unroll
    for (int i = 0; i < 4; i++)
#pragma unroll
        for (int j = 0; j < 8; j++)
#pragma unroll
            for (int t = 0; t < 4; t++) acc[i][j][t] = 0.0f;

    // loader chunk coords (16B granules)
    auto load_stage = [&](int s, int kt) {
        const int p  = kt / NCP;
        const int kc = (kt - p * NCP) * BK;
        const bf16* A = (p < 2) ? Ah : Al;
        const bf16* B = (p == 1) ? Bl : Bh;
        const uint32_t ast = sbase + s * STAGE_BYTES;
        const uint32_t bst = ast + A_BYTES;
#pragma unroll
        for (int h = 0; h < 4; h++) {            // A: 1024 chunks
            const int c = tid + h * 256;
            const int r = c >> 3, cc = c & 7;
            const uint32_t da = ast + r * 128 + ((cc * 16) ^ ((r & 7) * 16));
            const bf16* ga = A + (size_t)(m0 + r) * lda + kc + cc * 8;
            asm volatile("cp.async.cg.shared.global [%0], [%1], 16;" :: "r"(da), "l"(ga));
        }
#pragma unroll
        for (int h = 0; h < 8; h++) {            // B: 2048 chunks
            const int c = tid + h * 256;
            const int r = c >> 3, cc = c & 7;
            const uint32_t db = bst + r * 128 + ((cc * 16) ^ ((r & 7) * 16));
            const bf16* gb = B + (size_t)(n0 + r) * ldb + kc + cc * 8;
            asm volatile("cp.async.cg.shared.global [%0], [%1], 16;" :: "r"(db), "l"(gb));
        }
        asm volatile("cp.async.commit_group;" ::: "memory");
    };

#pragma unroll
    for (int s = 0; s < NSTAGE - 1; s++) load_stage(s, s);

    // per-lane ldmatrix address components (within stage)
    const uint32_t xorv = (l & 7) * 16;
    const int arow = wm + (l & 15);              // + 16*i
    const uint32_t acolb = (l >> 4) * 16;        // + 32*kk
    const int brow = wn + (l & 7) + (l >> 4) * 8; // + 16*j
    const uint32_t bcolb = ((l >> 3) & 1) * 16;  // + 32*kk

    for (int kt = 0; kt < NT; kt++) {
        const int cur = kt % NSTAGE;
        asm volatile("cp.async.wait_group %0;" :: "n"(NSTAGE - 2) : "memory");
        __syncthreads();
        if (kt + NSTAGE - 1 < NT) load_stage((kt + NSTAGE - 1) % NSTAGE, kt + NSTAGE - 1);

        const uint32_t ast = sbase + cur * STAGE_BYTES;
        const uint32_t bst = ast + A_BYTES;
#pragma unroll
        for (int kk = 0; kk < 4; kk++) {         // 4 x k16 per BK=64
            uint32_t af[4][4], bf[4][4];
#pragma unroll
            for (int i = 0; i < 4; i++)
                ldsm4(af[i], ast + (arow + 16 * i) * 128 + ((acolb + 32 * kk) ^ xorv));
#pragma unroll
            for (int j = 0; j < 4; j++)
                ldsm4(bf[j], bst + (brow + 16 * j) * 128 + ((bcolb + 32 * kk) ^ xorv));
#pragma unroll
            for (int i = 0; i < 4; i++)
#pragma unroll
                for (int j = 0; j < 8; j++)
                    mma16816(acc[i][j], af[i], &bf[j >> 1][(j & 1) * 2]);
        }
        __syncthreads();
    }

    // epilogue: c0,c1 -> (row, col..col+1); c2,c3 -> (row+8, ...)
    const int er = l >> 2, ec = (l & 3) * 2;
#pragma unroll
    for (int i = 0; i < 4; i++) {
        const int row = m0 + wm + 16 * i + er;
#pragma unroll
        for (int j = 0; j < 8; j++) {
            const int col = n0 + wn + 8 * j + ec;
            float2 v0 = {acc[i][j][0] * alpha, acc[i][j][1] * alpha};
            float2 v1 = {acc[i][j][2] * alpha, acc[i][j][3] * alpha};
            *(float2*)(C + (size_t)row * ldc + col) = v0;
            *(float2*)(C + (size_t)(row + 8) * ldc + col) = v1;
        }
    }
}

// ---------------- fp32 -> bf16 hi/lo split (no bias) ----------------
__global__ __launch_bounds__(256) void split_k(const float* __restrict__ in,
                                               bf16* __restrict__ h, bf16* __restrict__ l,
                                               int n4)
{
    int i = blockIdx.x * blockDim.x + threadIdx.x;
    if (i >= n4) return;
    float4 v = ((const float4*)in)[i];
    float vv[4] = {v.x, v.y, v.z, v.w};
    union { unsigned short u[4]; uint2 q; } hh, ll;
#pragma unroll
    for (int e = 0; e < 4; e++) {
        bf16 hb = __float2bfloat16(vv[e]);
        bf16 lb = __float2bfloat16(vv[e] - __bfloat162float(hb));
        hh.u[e] = *(unsigned short*)&hb;
        ll.u[e] = *(unsigned short*)&lb;
    }
    ((uint2*)h)[i] = hh.q;
    ((uint2*)l)[i] = ll.q;
}

// ---------------- fp32 + bias -> bf16 hi/lo split ----------------
__global__ __launch_bounds__(256) void bias_split_k(const float* __restrict__ in,
                                                    const float* __restrict__ bias,
                                                    bf16* __restrict__ h, bf16* __restrict__ l,
                                                    int n4)
{
    int i = blockIdx.x * blockDim.x + threadIdx.x;
    if (i >= n4) return;
    float4 v = ((const float4*)in)[i];
    const int col = (i * 4) % DIM;
    float4 bb = *(const float4*)(bias + col);
    float vv[4] = {v.x + bb.x, v.y + bb.y, v.z + bb.z, v.w + bb.w};
    union { unsigned short u[4]; uint2 q; } hh, ll;
#pragma unroll
    for (int e = 0; e < 4; e++) {
        bf16 hb = __float2bfloat16(vv[e]);
        bf16 lb = __float2bfloat16(vv[e] - __bfloat162float(hb));
        hh.u[e] = *(unsigned short*)&hb;
        ll.u[e] = *(unsigned short*)&lb;
    }
    ((uint2*)h)[i] = hh.q;
    ((uint2*)l)[i] = ll.q;
}

// ---------------- transpose V[b][s][d] -> Vt[b][d][s] (hi & lo) ----------------
__global__ void transpose_k(const bf16* __restrict__ vh, const bf16* __restrict__ vl,
                            bf16* __restrict__ th, bf16* __restrict__ tl)
{
    __shared__ bf16 sh[32][33], sl[32][33];
    const int z = blockIdx.z;
    const size_t ib = (size_t)z * SEQ * DIM;
    const int d0 = blockIdx.x * 32, s0 = blockIdx.y * 32;
    const int tx = threadIdx.x, ty = threadIdx.y;
#pragma unroll
    for (int i = 0; i < 32; i += 8) {
        sh[ty + i][tx] = vh[ib + (size_t)(s0 + ty + i) * DIM + d0 + tx];
        sl[ty + i][tx] = vl[ib + (size_t)(s0 + ty + i) * DIM + d0 + tx];
    }
    __syncthreads();
#pragma unroll
    for (int i = 0; i < 32; i += 8) {
        th[ib + (size_t)(d0 + ty + i) * SEQ + s0 + tx] = sh[tx][ty + i];
        tl[ib + (size_t)(d0 + ty + i) * SEQ + s0 + tx] = sl[tx][ty + i];
    }
}

// ---------------- softmax: fp32 scores row -> P hi/lo bf16 ----------------
__global__ __launch_bounds__(256) void softmax_k(const float* __restrict__ S,
                                                 bf16* __restrict__ ph, bf16* __restrict__ pl)
{
    const size_t rb = (size_t)blockIdx.x * SEQ;
    const float* p = S + rb;
    const int tid = threadIdx.x;

    float4 v[4];
#pragma unroll
    for (int i = 0; i < 4; i++) v[i] = *(const float4*)(p + tid * 4 + i * 1024);

    float m = -INFINITY;
#pragma unroll
    for (int i = 0; i < 4; i++)
        m = fmaxf(m, fmaxf(fmaxf(v[i].x, v[i].y), fmaxf(v[i].z, v[i].w)));

    __shared__ float red[256];
    red[tid] = m; __syncthreads();
#pragma unroll
    for (int s = 128; s > 0; s >>= 1) {
        if (tid < s) red[tid] = fmaxf(red[tid], red[tid + s]);
        __syncthreads();
    }
    m = red[0]; __syncthreads();

    float sum = 0.0f;
#pragma unroll
    for (int i = 0; i < 4; i++) {
        v[i].x = __expf(v[i].x - m); v[i].y = __expf(v[i].y - m);
        v[i].z = __expf(v[i].z - m); v[i].w = __expf(v[i].w - m);
        sum += v[i].x + v[i].y + v[i].z + v[i].w;
    }
    red[tid] = sum; __syncthreads();
#pragma unroll
    for (int s = 128; s > 0; s >>= 1) {
        if (tid < s) red[tid] += red[tid + s];
        __syncthreads();
    }
    const float inv = 1.0f / red[0];

#pragma unroll
    for (int i = 0; i < 4; i++) {
        float vv[4] = {v[i].x * inv, v[i].y * inv, v[i].z * inv, v[i].w * inv};
        union { unsigned short u[4]; uint2 q; } hh, ll;
#pragma unroll
        for (int e = 0; e < 4; e++) {
            bf16 hb = __float2bfloat16(vv[e]);
            bf16 lb = __float2bfloat16(vv[e] - __bfloat162float(hb));
            hh.u[e] = *(unsigned short*)&hb;
            ll.u[e] = *(unsigned short*)&lb;
        }
        *(uint2*)(ph + rb + tid * 4 + i * 1024) = hh.q;
        *(uint2*)(pl + rb + tid * 4 + i * 1024) = ll.q;
    }
}

// ---------------- launch ----------------
extern "C" void kernel_launch(void* const* d_in, const int* in_sizes, int n_in,
                              void* d_out, int out_size)
{
    const float* x  = (const float*)d_in[0];
    const float* Wq = (const float*)d_in[1];
    const float* bq = (const float*)d_in[2];
    const float* Wk = (const float*)d_in[3];
    const float* bk = (const float*)d_in[4];
    const float* Wv = (const float*)d_in[5];
    const float* bv = (const float*)d_in[6];
    float* out = (float*)d_out;

    bf16 *xh, *xl, *wqh, *wql, *wkh, *wkl, *wvh, *wvl;
    bf16 *qh, *ql, *kh, *kl, *vh, *vl, *vth, *vtl, *pph, *ppl;
    float *qf, *kf, *vf, *sc;
    cudaGetSymbolAddress((void**)&xh, g_xh);   cudaGetSymbolAddress((void**)&xl, g_xl);
    cudaGetSymbolAddress((void**)&wqh, g_wqh); cudaGetSymbolAddress((void**)&wql, g_wql);
    cudaGetSymbolAddress((void**)&wkh, g_wkh); cudaGetSymbolAddress((void**)&wkl, g_wkl);
    cudaGetSymbolAddress((void**)&wvh, g_wvh); cudaGetSymbolAddress((void**)&wvl, g_wvl);
    cudaGetSymbolAddress((void**)&qf, g_qf);   cudaGetSymbolAddress((void**)&kf, g_kf);
    cudaGetSymbolAddress((void**)&vf, g_vf);
    cudaGetSymbolAddress((void**)&qh, g_qh);   cudaGetSymbolAddress((void**)&ql, g_ql);
    cudaGetSymbolAddress((void**)&kh, g_kh);   cudaGetSymbolAddress((void**)&kl, g_kl);
    cudaGetSymbolAddress((void**)&vh, g_vh);   cudaGetSymbolAddress((void**)&vl, g_vl);
    cudaGetSymbolAddress((void**)&vth, g_vth); cudaGetSymbolAddress((void**)&vtl, g_vtl);
    cudaGetSymbolAddress((void**)&pph, g_ph);  cudaGetSymbolAddress((void**)&ppl, g_pl);
    cudaGetSymbolAddress((void**)&sc, g_s);

    cudaFuncSetAttribute(gemm_mma, cudaFuncAttributeMaxDynamicSharedMemorySize, GEMM_SMEM);

    const float scale = 1.0f / sqrtf((float)DIM);

    // 1. split inputs to bf16 hi/lo
    split_k<<<(int)(NTD / 4 + 255) / 256, 256>>>(x, xh, xl, (int)(NTD / 4));
    split_k<<<(int)(WSZ / 4 + 255) / 256, 256>>>(Wq, wqh, wql, (int)(WSZ / 4));
    split_k<<<(int)(WSZ / 4 + 255) / 256, 256>>>(Wk, wkh, wkl, (int)(WSZ / 4));
    split_k<<<(int)(WSZ / 4 + 255) / 256, 256>>>(Wv, wvh, wvl, (int)(WSZ / 4));

    // 2. projections: [16384,768] = x * W^T  (fp32 out)
    dim3 gp(NTOK / BM, DIM / BN, 1);
    gemm_mma<<<gp, 256, GEMM_SMEM>>>(xh, xl, wqh, wql, qf, DIM, DIM, DIM, DIM, 1.0f, 0, 0, 0);
    gemm_mma<<<gp, 256, GEMM_SMEM>>>(xh, xl, wkh, wkl, kf, DIM, DIM, DIM, DIM, 1.0f, 0, 0, 0);
    gemm_mma<<<gp, 256, GEMM_SMEM>>>(xh, xl, wvh, wvl, vf, DIM, DIM, DIM, DIM, 1.0f, 0, 0, 0);

    // 3. bias + split to bf16 hi/lo
    bias_split_k<<<(int)(NTD / 4 + 255) / 256, 256>>>(qf, bq, qh, ql, (int)(NTD / 4));
    bias_split_k<<<(int)(NTD / 4 + 255) / 256, 256>>>(kf, bk, kh, kl, (int)(NTD / 4));
    bias_split_k<<<(int)(NTD / 4 + 255) / 256, 256>>>(vf, bv, vh, vl, (int)(NTD / 4));

    // 4. transpose V -> Vt[b][d][s]
    transpose_k<<<dim3(DIM / 32, SEQ / 32, BATCH), dim3(32, 8)>>>(vh, vl, vth, vtl);

    // 5. scores[b] = scale * Q[b] K[b]^T
    gemm_mma<<<dim3(SEQ / BM, SEQ / BN, BATCH), 256, GEMM_SMEM>>>(
        qh, ql, kh, kl, sc, DIM, DIM, DIM, SEQ, scale,
        (size_t)SEQ * DIM, (size_t)SEQ * DIM, (size_t)SEQ * SEQ);

    // 6. softmax rows -> P hi/lo
    softmax_k<<<NTOK, 256>>>(sc, pph, ppl);

    // 7. out[b] = P[b] V[b]   (B operand = Vt, K-major over seq)
    gemm_mma<<<dim3(SEQ / BM, DIM / BN, BATCH), 256, GEMM_SMEM>>>(
        pph, ppl, vth, vtl, out, SEQ, SEQ, SEQ, DIM, 1.0f,
        (size_t)SEQ * SEQ, (size_t)SEQ * DIM, (size_t)SEQ * DIM);

    (void)in_sizes; (void)n_in; (void)out_size;
}

// round 10
// speedup vs baseline: 2.6561x; 1.0247x over previous
#include <cuda_runtime.h>
#include <cuda_bf16.h>
#include <cstdint>
#include <math.h>

using bf16 = __nv_bfloat16;

#define BATCH 4
#define SEQ   4096
#define DIM   768
#define NTOK  (BATCH * SEQ)                 // 16384
#define NTD   ((size_t)NTOK * DIM)
#define WSZ   ((size_t)DIM * DIM)
#define SSZ   ((size_t)BATCH * SEQ * SEQ)

// ---------------- device scratch (allocation-free rule) ----------------
__device__ bf16  g_xh[NTD], g_xl[NTD];
__device__ bf16  g_wqh[WSZ], g_wql[WSZ], g_wkh[WSZ], g_wkl[WSZ], g_wvh[WSZ], g_wvl[WSZ];
__device__ bf16  g_qh[NTD], g_ql[NTD], g_kh[NTD], g_kl[NTD], g_vh[NTD], g_vl[NTD];
__device__ bf16  g_vth[NTD], g_vtl[NTD];    // V transposed: [b][dim][seq]
__device__ float g_s[SSZ];                  // scores fp32
__device__ bf16  g_ph[SSZ], g_pl[SSZ];      // softmax probs hi/lo

__device__ __forceinline__ uint32_t smem_u32(const void* p) {
    uint32_t a;
    asm("{ .reg .u64 t; cvta.to.shared.u64 t, %1; cvt.u32.u64 %0, t; }" : "=r"(a) : "l"(p));
    return a;
}

__device__ __forceinline__ void ldsm4(uint32_t* r, uint32_t addr) {
    asm volatile("ldmatrix.sync.aligned.m8n8.x4.shared.b16 {%0,%1,%2,%3}, [%4];"
                 : "=r"(r[0]), "=r"(r[1]), "=r"(r[2]), "=r"(r[3]) : "r"(addr));
}
__device__ __forceinline__ void mma16816(float* d, const uint32_t* a, const uint32_t* b) {
    asm volatile("mma.sync.aligned.m16n8k16.row.col.f32.bf16.bf16.f32 "
                 "{%0,%1,%2,%3}, {%4,%5,%6,%7}, {%8,%9}, {%0,%1,%2,%3};"
                 : "+f"(d[0]), "+f"(d[1]), "+f"(d[2]), "+f"(d[3])
                 : "r"(a[0]), "r"(a[1]), "r"(a[2]), "r"(a[3]), "r"(b[0]), "r"(b[1]));
}

__device__ __forceinline__ uint32_t pack_bf2(float a, float b) {
    __nv_bfloat162 t = __floats2bfloat162_rn(a, b);
    return *(uint32_t*)&t;
}

// ---------------------------------------------------------------------------
// NT GEMM via raw mma.sync + ldmatrix, 3-pass bf16 hi/lo split:
//   acc[M,N] = Ah*Bh^T + Ah*Bl^T + Al*Bh^T
// MODE 0: C = alpha * acc (fp32)
// MODE 1: t = acc + bias[col]; Oh/Ol = hi/lo bf16 split of t
// CTA tile 128x256, BK=64, 256 threads (8 warps 2x4, warp tile 64x64).
// 3-stage cp.async pipeline; smem rows 128B with XOR-16B swizzle.
// Requires M%128==0, N%256==0, K%64==0.
// ---------------------------------------------------------------------------
#define BM 128
#define BN 256
#define BK 64
#define A_BYTES (BM * 128)                 // 16384
#define B_BYTES (BN * 128)                 // 32768
#define STAGE_BYTES (A_BYTES + B_BYTES)    // 49152
#define NSTAGE 3
#define GEMM_SMEM (NSTAGE * STAGE_BYTES)   // 147456

template <int MODE>
__global__ __launch_bounds__(256, 1) void gemm_mma(
    const bf16* __restrict__ Ah, const bf16* __restrict__ Al,
    const bf16* __restrict__ Bh, const bf16* __restrict__ Bl,
    float* __restrict__ C, const float* __restrict__ bias,
    bf16* __restrict__ Oh, bf16* __restrict__ Ol,
    int K, int lda, int ldb, int ldc, float alpha,
    size_t sA, size_t sB, size_t sC)
{
    extern __shared__ char smem[];
    const uint32_t sbase = smem_u32(smem);

    const int tid = threadIdx.x;
    const int wid = tid >> 5;
    const int l   = tid & 31;
    const int m0 = blockIdx.x * BM;
    const int n0 = blockIdx.y * BN;
    const int z  = blockIdx.z;
    Ah += (size_t)z * sA; Al += (size_t)z * sA;
    Bh += (size_t)z * sB; Bl += (size_t)z * sB;

    const int NCP = K / BK;
    const int NT  = 3 * NCP;      // hi*hi, hi*lo, lo*hi

    const int wm = (wid >> 2) * 64;   // warp M offset in CTA tile
    const int wn = (wid & 3) * 64;    // warp N offset

    float acc[4][8][4];
#pragma unroll
    for (int i = 0; i < 4; i++)
#pragma unroll
        for (int j = 0; j < 8; j++)
#pragma unroll
            for (int t = 0; t < 4; t++) acc[i][j][t] = 0.0f;

    auto load_stage = [&](int s, int kt) {
        const int p  = kt / NCP;
        const int kc = (kt - p * NCP) * BK;
        const bf16* A = (p < 2) ? Ah : Al;
        const bf16* B = (p == 1) ? Bl : Bh;
        const uint32_t ast = sbase + s * STAGE_BYTES;
        const uint32_t bst = ast + A_BYTES;
#pragma unroll
        for (int h = 0; h < 4; h++) {            // A: 1024 16B chunks
            const int c = tid + h * 256;
            const int r = c >> 3, cc = c & 7;
            const uint32_t da = ast + r * 128 + ((cc * 16) ^ ((r & 7) * 16));
            const bf16* ga = A + (size_t)(m0 + r) * lda + kc + cc * 8;
            asm volatile("cp.async.cg.shared.global [%0], [%1], 16;" :: "r"(da), "l"(ga));
        }
#pragma unroll
        for (int h = 0; h < 8; h++) {            // B: 2048 16B chunks
            const int c = tid + h * 256;
            const int r = c >> 3, cc = c & 7;
            const uint32_t db = bst + r * 128 + ((cc * 16) ^ ((r & 7) * 16));
            const bf16* gb = B + (size_t)(n0 + r) * ldb + kc + cc * 8;
            asm volatile("cp.async.cg.shared.global [%0], [%1], 16;" :: "r"(db), "l"(gb));
        }
        asm volatile("cp.async.commit_group;" ::: "memory");
    };

#pragma unroll
    for (int s = 0; s < NSTAGE - 1; s++) load_stage(s, s);

    // per-lane ldmatrix address components (within stage)
    const uint32_t xorv = (l & 7) * 16;
    const int arow = wm + (l & 15);               // + 16*i
    const uint32_t acolb = (l >> 4) * 16;         // + 32*kk
    const int brow = wn + (l & 7) + (l >> 4) * 8; // + 16*j
    const uint32_t bcolb = ((l >> 3) & 1) * 16;   // + 32*kk

    for (int kt = 0; kt < NT; kt++) {
        const int cur = kt % NSTAGE;
        asm volatile("cp.async.wait_group %0;" :: "n"(NSTAGE - 2) : "memory");
        __syncthreads();
        if (kt + NSTAGE - 1 < NT) load_stage((kt + NSTAGE - 1) % NSTAGE, kt + NSTAGE - 1);

        const uint32_t ast = sbase + cur * STAGE_BYTES;
        const uint32_t bst = ast + A_BYTES;
#pragma unroll
        for (int kk = 0; kk < 4; kk++) {         // 4 x k16 per BK=64
            uint32_t af[4][4], bf[4][4];
#pragma unroll
            for (int i = 0; i < 4; i++)
                ldsm4(af[i], ast + (arow + 16 * i) * 128 + ((acolb + 32 * kk) ^ xorv));
#pragma unroll
            for (int j = 0; j < 4; j++)
                ldsm4(bf[j], bst + (brow + 16 * j) * 128 + ((bcolb + 32 * kk) ^ xorv));
#pragma unroll
            for (int i = 0; i < 4; i++)
#pragma unroll
                for (int j = 0; j < 8; j++)
                    mma16816(acc[i][j], af[i], &bf[j >> 1][(j & 1) * 2]);
        }
        // NOTE: no trailing barrier — the next iteration's top barrier protects
        // the stage ring (write target (kt+2)%3 == read stage of iter kt-1).
    }

    // epilogue: c0,c1 -> (row, col..col+1); c2,c3 -> (row+8, ...)
    const int er = l >> 2, ec = (l & 3) * 2;
#pragma unroll
    for (int i = 0; i < 4; i++) {
        const int row = m0 + wm + 16 * i + er;
#pragma unroll
        for (int j = 0; j < 8; j++) {
            const int col = n0 + wn + 8 * j + ec;
            if (MODE == 0) {
                float* Cz = C + (size_t)z * sC;
                float2 v0 = {acc[i][j][0] * alpha, acc[i][j][1] * alpha};
                float2 v1 = {acc[i][j][2] * alpha, acc[i][j][3] * alpha};
                *(float2*)(Cz + (size_t)row * ldc + col) = v0;
                *(float2*)(Cz + (size_t)(row + 8) * ldc + col) = v1;
            } else {
                const float b0 = bias[col], b1 = bias[col + 1];
                float t00 = acc[i][j][0] + b0, t01 = acc[i][j][1] + b1;
                float t10 = acc[i][j][2] + b0, t11 = acc[i][j][3] + b1;
                bf16 h00 = __float2bfloat16(t00), h01 = __float2bfloat16(t01);
                bf16 h10 = __float2bfloat16(t10), h11 = __float2bfloat16(t11);
                float l00 = t00 - __bfloat162float(h00), l01 = t01 - __bfloat162float(h01);
                float l10 = t10 - __bfloat162float(h10), l11 = t11 - __bfloat162float(h11);
                uint32_t hp0, hp1;
                { __nv_bfloat162 t = {h00, h01}; hp0 = *(uint32_t*)&t; }
                { __nv_bfloat162 t = {h10, h11}; hp1 = *(uint32_t*)&t; }
                *(uint32_t*)(Oh + (size_t)row * ldc + col) = hp0;
                *(uint32_t*)(Oh + (size_t)(row + 8) * ldc + col) = hp1;
                *(uint32_t*)(Ol + (size_t)row * ldc + col) = pack_bf2(l00, l01);
                *(uint32_t*)(Ol + (size_t)(row + 8) * ldc + col) = pack_bf2(l10, l11);
            }
        }
    }
}

// ---------------- fp32 -> bf16 hi/lo split (no bias) ----------------
__global__ __launch_bounds__(256) void split_k(const float* __restrict__ in,
                                               bf16* __restrict__ h, bf16* __restrict__ l,
                                               int n4)
{
    int i = blockIdx.x * blockDim.x + threadIdx.x;
    if (i >= n4) return;
    float4 v = ((const float4*)in)[i];
    float vv[4] = {v.x, v.y, v.z, v.w};
    union { unsigned short u[4]; uint2 q; } hh, ll;
#pragma unroll
    for (int e = 0; e < 4; e++) {
        bf16 hb = __float2bfloat16(vv[e]);
        bf16 lb = __float2bfloat16(vv[e] - __bfloat162float(hb));
        hh.u[e] = *(unsigned short*)&hb;
        ll.u[e] = *(unsigned short*)&lb;
    }
    ((uint2*)h)[i] = hh.q;
    ((uint2*)l)[i] = ll.q;
}

// ---------------- transpose V[b][s][d] -> Vt[b][d][s] (hi & lo) ----------------
__global__ void transpose_k(const bf16* __restrict__ vh, const bf16* __restrict__ vl,
                            bf16* __restrict__ th, bf16* __restrict__ tl)
{
    __shared__ bf16 sh[32][33], sl[32][33];
    const int z = blockIdx.z;
    const size_t ib = (size_t)z * SEQ * DIM;
    const int d0 = blockIdx.x * 32, s0 = blockIdx.y * 32;
    const int tx = threadIdx.x, ty = threadIdx.y;
#pragma unroll
    for (int i = 0; i < 32; i += 8) {
        sh[ty + i][tx] = vh[ib + (size_t)(s0 + ty + i) * DIM + d0 + tx];
        sl[ty + i][tx] = vl[ib + (size_t)(s0 + ty + i) * DIM + d0 + tx];
    }
    __syncthreads();
#pragma unroll
    for (int i = 0; i < 32; i += 8) {
        th[ib + (size_t)(d0 + ty + i) * SEQ + s0 + tx] = sh[tx][ty + i];
        tl[ib + (size_t)(d0 + ty + i) * SEQ + s0 + tx] = sl[tx][ty + i];
    }
}

// ---------------- softmax: fp32 scores row -> P hi/lo bf16 ----------------
__global__ __launch_bounds__(256) void softmax_k(const float* __restrict__ S,
                                                 bf16* __restrict__ ph, bf16* __restrict__ pl)
{
    const size_t rb = (size_t)blockIdx.x * SEQ;
    const float* p = S + rb;
    const int tid = threadIdx.x;

    float4 v[4];
#pragma unroll
    for (int i = 0; i < 4; i++) v[i] = *(const float4*)(p + tid * 4 + i * 1024);

    float m = -INFINITY;
#pragma unroll
    for (int i = 0; i < 4; i++)
        m = fmaxf(m, fmaxf(fmaxf(v[i].x, v[i].y), fmaxf(v[i].z, v[i].w)));

    __shared__ float red[256];
    red[tid] = m; __syncthreads();
#pragma unroll
    for (int s = 128; s > 0; s >>= 1) {
        if (tid < s) red[tid] = fmaxf(red[tid], red[tid + s]);
        __syncthreads();
    }
    m = red[0]; __syncthreads();

    float sum = 0.0f;
#pragma unroll
    for (int i = 0; i < 4; i++) {
        v[i].x = __expf(v[i].x - m); v[i].y = __expf(v[i].y - m);
        v[i].z = __expf(v[i].z - m); v[i].w = __expf(v[i].w - m);
        sum += v[i].x + v[i].y + v[i].z + v[i].w;
    }
    red[tid] = sum; __syncthreads();
#pragma unroll
    for (int s = 128; s > 0; s >>= 1) {
        if (tid < s) red[tid] += red[tid + s];
        __syncthreads();
    }
    const float inv = 1.0f / red[0];

#pragma unroll
    for (int i = 0; i < 4; i++) {
        float vv[4] = {v[i].x * inv, v[i].y * inv, v[i].z * inv, v[i].w * inv};
        union { unsigned short u[4]; uint2 q; } hh, ll;
#pragma unroll
        for (int e = 0; e < 4; e++) {
            bf16 hb = __float2bfloat16(vv[e]);
            bf16 lb = __float2bfloat16(vv[e] - __bfloat162float(hb));
            hh.u[e] = *(unsigned short*)&hb;
            ll.u[e] = *(unsigned short*)&lb;
        }
        *(uint2*)(ph + rb + tid * 4 + i * 1024) = hh.q;
        *(uint2*)(pl + rb + tid * 4 + i * 1024) = ll.q;
    }
}

// ---------------- launch ----------------
extern "C" void kernel_launch(void* const* d_in, const int* in_sizes, int n_in,
                              void* d_out, int out_size)
{
    const float* x  = (const float*)d_in[0];
    const float* Wq = (const float*)d_in[1];
    const float* bq = (const float*)d_in[2];
    const float* Wk = (const float*)d_in[3];
    const float* bk = (const float*)d_in[4];
    const float* Wv = (const float*)d_in[5];
    const float* bv = (const float*)d_in[6];
    float* out = (float*)d_out;

    bf16 *xh, *xl, *wqh, *wql, *wkh, *wkl, *wvh, *wvl;
    bf16 *qh, *ql, *kh, *kl, *vh, *vl, *vth, *vtl, *pph, *ppl;
    float *sc;
    cudaGetSymbolAddress((void**)&xh, g_xh);   cudaGetSymbolAddress((void**)&xl, g_xl);
    cudaGetSymbolAddress((void**)&wqh, g_wqh); cudaGetSymbolAddress((void**)&wql, g_wql);
    cudaGetSymbolAddress((void**)&wkh, g_wkh); cudaGetSymbolAddress((void**)&wkl, g_wkl);
    cudaGetSymbolAddress((void**)&wvh, g_wvh); cudaGetSymbolAddress((void**)&wvl, g_wvl);
    cudaGetSymbolAddress((void**)&qh, g_qh);   cudaGetSymbolAddress((void**)&ql, g_ql);
    cudaGetSymbolAddress((void**)&kh, g_kh);   cudaGetSymbolAddress((void**)&kl, g_kl);
    cudaGetSymbolAddress((void**)&vh, g_vh);   cudaGetSymbolAddress((void**)&vl, g_vl);
    cudaGetSymbolAddress((void**)&vth, g_vth); cudaGetSymbolAddress((void**)&vtl, g_vtl);
    cudaGetSymbolAddress((void**)&pph, g_ph);  cudaGetSymbolAddress((void**)&ppl, g_pl);
    cudaGetSymbolAddress((void**)&sc, g_s);

    cudaFuncSetAttribute(gemm_mma<0>, cudaFuncAttributeMaxDynamicSharedMemorySize, GEMM_SMEM);
    cudaFuncSetAttribute(gemm_mma<1>, cudaFuncAttributeMaxDynamicSharedMemorySize, GEMM_SMEM);

    const float scale = 1.0f / sqrtf((float)DIM);

    // 1. split inputs to bf16 hi/lo
    split_k<<<(int)(NTD / 4 + 255) / 256, 256>>>(x, xh, xl, (int)(NTD / 4));
    split_k<<<(int)(WSZ / 4 + 255) / 256, 256>>>(Wq, wqh, wql, (int)(WSZ / 4));
    split_k<<<(int)(WSZ / 4 + 255) / 256, 256>>>(Wk, wkh, wkl, (int)(WSZ / 4));
    split_k<<<(int)(WSZ / 4 + 255) / 256, 256>>>(Wv, wvh, wvl, (int)(WSZ / 4));

    // 2. projections with fused bias + hi/lo split epilogue
    dim3 gp(NTOK / BM, DIM / BN, 1);
    gemm_mma<1><<<gp, 256, GEMM_SMEM>>>(xh, xl, wqh, wql, nullptr, bq, qh, ql,
                                        DIM, DIM, DIM, DIM, 1.0f, 0, 0, 0);
    gemm_mma<1><<<gp, 256, GEMM_SMEM>>>(xh, xl, wkh, wkl, nullptr, bk, kh, kl,
                                        DIM, DIM, DIM, DIM, 1.0f, 0, 0, 0);
    gemm_mma<1><<<gp, 256, GEMM_SMEM>>>(xh, xl, wvh, wvl, nullptr, bv, vh, vl,
                                        DIM, DIM, DIM, DIM, 1.0f, 0, 0, 0);

    // 3. transpose V -> Vt[b][d][s]
    transpose_k<<<dim3(DIM / 32, SEQ / 32, BATCH), dim3(32, 8)>>>(vh, vl, vth, vtl);

    // 4. scores[b] = scale * Q[b] K[b]^T
    gemm_mma<0><<<dim3(SEQ / BM, SEQ / BN, BATCH), 256, GEMM_SMEM>>>(
        qh, ql, kh, kl, sc, nullptr, nullptr, nullptr,
        DIM, DIM, DIM, SEQ, scale,
        (size_t)SEQ * DIM, (size_t)SEQ * DIM, (size_t)SEQ * SEQ);

    // 5. softmax rows -> P hi/lo
    softmax_k<<<NTOK, 256>>>(sc, pph, ppl);

    // 6. out[b] = P[b] V[b]   (B operand = Vt, K-major over seq)
    gemm_mma<0><<<dim3(SEQ / BM, DIM / BN, BATCH), 256, GEMM_SMEM>>>(
        pph, ppl, vth, vtl, out, nullptr, nullptr, nullptr,
        SEQ, SEQ, SEQ, DIM, 1.0f,
        (size_t)SEQ * SEQ, (size_t)SEQ * DIM, (size_t)SEQ * DIM);

    (void)in_sizes; (void)n_in; (void)out_size;
}

// round 12
// speedup vs baseline: 2.7182x; 1.0234x over previous
#include <cuda_runtime.h>
#include <cuda_bf16.h>
#include <cstdint>
#include <math.h>

using bf16 = __nv_bfloat16;

#define BATCH 4
#define SEQ   4096
#define DIM   768
#define QKV   (3 * DIM)                     // 2304
#define NTOK  (BATCH * SEQ)                 // 16384
#define NTD   ((size_t)NTOK * DIM)
#define NTQ   ((size_t)NTOK * QKV)
#define WSZ   ((size_t)DIM * DIM)
#define SSZ   ((size_t)BATCH * SEQ * SEQ)

// ---------------- device scratch (allocation-free rule) ----------------
__device__ bf16  g_xh[NTD], g_xl[NTD];
__device__ bf16  g_wch[3 * WSZ], g_wcl[3 * WSZ];   // [Wq;Wk;Wv] hi/lo
__device__ float g_bias[QKV];
__device__ bf16  g_qkvh[NTQ], g_qkvl[NTQ];         // fused q|k|v, ld = 2304
__device__ bf16  g_vth[NTD], g_vtl[NTD];           // V transposed: [b][dim][seq]
__device__ float g_s[SSZ];                         // scores fp32
__device__ bf16  g_ph[SSZ], g_pl[SSZ];             // softmax probs hi/lo

__device__ __forceinline__ uint32_t smem_u32(const void* p) {
    uint32_t a;
    asm("{ .reg .u64 t; cvta.to.shared.u64 t, %1; cvt.u32.u64 %0, t; }" : "=r"(a) : "l"(p));
    return a;
}

__device__ __forceinline__ void ldsm4(uint32_t* r, uint32_t addr) {
    asm volatile("ldmatrix.sync.aligned.m8n8.x4.shared.b16 {%0,%1,%2,%3}, [%4];"
                 : "=r"(r[0]), "=r"(r[1]), "=r"(r[2]), "=r"(r[3]) : "r"(addr));
}
__device__ __forceinline__ void mma16816(float* d, const uint32_t* a, const uint32_t* b) {
    asm volatile("mma.sync.aligned.m16n8k16.row.col.f32.bf16.bf16.f32 "
                 "{%0,%1,%2,%3}, {%4,%5,%6,%7}, {%8,%9}, {%0,%1,%2,%3};"
                 : "+f"(d[0]), "+f"(d[1]), "+f"(d[2]), "+f"(d[3])
                 : "r"(a[0]), "r"(a[1]), "r"(a[2]), "r"(a[3]), "r"(b[0]), "r"(b[1]));
}

__device__ __forceinline__ uint32_t pack_bf2(float a, float b) {
    __nv_bfloat162 t = __floats2bfloat162_rn(a, b);
    return *(uint32_t*)&t;
}

// ---------------------------------------------------------------------------
// NT GEMM via raw mma.sync + ldmatrix, 3-pass bf16 hi/lo split:
//   acc[M,N] = Ah*Bh^T + Ah*Bl^T + Al*Bh^T
// MODE 0: C = alpha * acc (fp32)
// MODE 1: t = acc + bias[col]; Oh/Ol = hi/lo bf16 split of t  (ld = ldc)
// CTA tile 128x256, BK=64, 256 threads (8 warps 2x4, warp tile 64x64).
// 3-stage cp.async pipeline; smem rows 128B, XOR-16B swizzle;
// double-buffered ldmatrix fragments inside the k-tile.
// Requires M%128==0, N%256==0, K%64==0, 16B-aligned rows.
// ---------------------------------------------------------------------------
#define BM 128
#define BN 256
#define BK 64
#define A_BYTES (BM * 128)                 // 16384
#define B_BYTES (BN * 128)                 // 32768
#define STAGE_BYTES (A_BYTES + B_BYTES)    // 49152
#define NSTAGE 3
#define GEMM_SMEM (NSTAGE * STAGE_BYTES)   // 147456

template <int MODE>
__global__ __launch_bounds__(256, 1) void gemm_mma(
    const bf16* __restrict__ Ah, const bf16* __restrict__ Al,
    const bf16* __restrict__ Bh, const bf16* __restrict__ Bl,
    float* __restrict__ C, const float* __restrict__ bias,
    bf16* __restrict__ Oh, bf16* __restrict__ Ol,
    int K, int lda, int ldb, int ldc, float alpha,
    size_t sA, size_t sB, size_t sC)
{
    extern __shared__ char smem[];
    const uint32_t sbase = smem_u32(smem);

    const int tid = threadIdx.x;
    const int wid = tid >> 5;
    const int l   = tid & 31;
    const int m0 = blockIdx.x * BM;
    const int n0 = blockIdx.y * BN;
    const int z  = blockIdx.z;
    Ah += (size_t)z * sA; Al += (size_t)z * sA;
    Bh += (size_t)z * sB; Bl += (size_t)z * sB;

    const int NCP = K / BK;
    const int NT  = 3 * NCP;      // hi*hi, hi*lo, lo*hi

    const int wm = (wid >> 2) * 64;   // warp M offset in CTA tile
    const int wn = (wid & 3) * 64;    // warp N offset

    float acc[4][8][4];
#pragma unroll
    for (int i = 0; i < 4; i++)
#pragma unroll
        for (int j = 0; j < 8; j++)
#pragma unroll
            for (int t = 0; t < 4; t++) acc[i][j][t] = 0.0f;

    auto load_stage = [&](int s, int kt) {
        const int p  = kt / NCP;
        const int kc = (kt - p * NCP) * BK;
        const bf16* A = (p < 2) ? Ah : Al;
        const bf16* B = (p == 1) ? Bl : Bh;
        const uint32_t ast = sbase + s * STAGE_BYTES;
        const uint32_t bst = ast + A_BYTES;
#pragma unroll
        for (int h = 0; h < 4; h++) {            // A: 1024 16B chunks
            const int c = tid + h * 256;
            const int r = c >> 3, cc = c & 7;
            const uint32_t da = ast + r * 128 + ((cc * 16) ^ ((r & 7) * 16));
            const bf16* ga = A + (size_t)(m0 + r) * lda + kc + cc * 8;
            asm volatile("cp.async.cg.shared.global [%0], [%1], 16;" :: "r"(da), "l"(ga));
        }
#pragma unroll
        for (int h = 0; h < 8; h++) {            // B: 2048 16B chunks
            const int c = tid + h * 256;
            const int r = c >> 3, cc = c & 7;
            const uint32_t db = bst + r * 128 + ((cc * 16) ^ ((r & 7) * 16));
            const bf16* gb = B + (size_t)(n0 + r) * ldb + kc + cc * 8;
            asm volatile("cp.async.cg.shared.global [%0], [%1], 16;" :: "r"(db), "l"(gb));
        }
        asm volatile("cp.async.commit_group;" ::: "memory");
    };

#pragma unroll
    for (int s = 0; s < NSTAGE - 1; s++) load_stage(s, s);

    // per-lane ldmatrix address components (within stage)
    const uint32_t xorv = (l & 7) * 16;
    const int arow = wm + (l & 15);               // + 16*i
    const uint32_t acolb = (l >> 4) * 16;         // + 32*kk
    const int brow = wn + (l & 7) + (l >> 4) * 8; // + 16*j
    const uint32_t bcolb = ((l >> 3) & 1) * 16;   // + 32*kk

    for (int kt = 0; kt < NT; kt++) {
        const int cur = kt % NSTAGE;
        asm volatile("cp.async.wait_group %0;" :: "n"(NSTAGE - 2) : "memory");
        __syncthreads();
        if (kt + NSTAGE - 1 < NT) load_stage((kt + NSTAGE - 1) % NSTAGE, kt + NSTAGE - 1);

        const uint32_t ast = sbase + cur * STAGE_BYTES;
        const uint32_t bst = ast + A_BYTES;

        // double-buffered fragments: prefetch kk+1 while issuing kk's MMAs
        uint32_t af[2][4][4], bf[2][4][4];
#pragma unroll
        for (int i = 0; i < 4; i++)
            ldsm4(af[0][i], ast + (arow + 16 * i) * 128 + (acolb ^ xorv));
#pragma unroll
        for (int j = 0; j < 4; j++)
            ldsm4(bf[0][j], bst + (brow + 16 * j) * 128 + (bcolb ^ xorv));

#pragma unroll
        for (int kk = 0; kk < 4; kk++) {         // 4 x k16 per BK=64
            const int cb = kk & 1, nb = cb ^ 1;
            if (kk < 3) {
#pragma unroll
                for (int i = 0; i < 4; i++)
                    ldsm4(af[nb][i],
                          ast + (arow + 16 * i) * 128 + ((acolb + 32 * (kk + 1)) ^ xorv));
#pragma unroll
                for (int j = 0; j < 4; j++)
                    ldsm4(bf[nb][j],
                          bst + (brow + 16 * j) * 128 + ((bcolb + 32 * (kk + 1)) ^ xorv));
            }
#pragma unroll
            for (int i = 0; i < 4; i++)
#pragma unroll
                for (int j = 0; j < 8; j++)
                    mma16816(acc[i][j], af[cb][i], &bf[cb][j >> 1][(j & 1) * 2]);
        }
        // no trailing barrier: next iteration's top barrier protects the ring
    }

    // epilogue: c0,c1 -> (row, col..col+1); c2,c3 -> (row+8, ...)
    const int er = l >> 2, ec = (l & 3) * 2;
#pragma unroll
    for (int i = 0; i < 4; i++) {
        const int row = m0 + wm + 16 * i + er;
#pragma unroll
        for (int j = 0; j < 8; j++) {
            const int col = n0 + wn + 8 * j + ec;
            if (MODE == 0) {
                float* Cz = C + (size_t)z * sC;
                float2 v0 = {acc[i][j][0] * alpha, acc[i][j][1] * alpha};
                float2 v1 = {acc[i][j][2] * alpha, acc[i][j][3] * alpha};
                *(float2*)(Cz + (size_t)row * ldc + col) = v0;
                *(float2*)(Cz + (size_t)(row + 8) * ldc + col) = v1;
            } else {
                const float b0 = bias[col], b1 = bias[col + 1];
                float t00 = acc[i][j][0] + b0, t01 = acc[i][j][1] + b1;
                float t10 = acc[i][j][2] + b0, t11 = acc[i][j][3] + b1;
                bf16 h00 = __float2bfloat16(t00), h01 = __float2bfloat16(t01);
                bf16 h10 = __float2bfloat16(t10), h11 = __float2bfloat16(t11);
                float l00 = t00 - __bfloat162float(h00), l01 = t01 - __bfloat162float(h01);
                float l10 = t10 - __bfloat162float(h10), l11 = t11 - __bfloat162float(h11);
                uint32_t hp0, hp1;
                { __nv_bfloat162 t = {h00, h01}; hp0 = *(uint32_t*)&t; }
                { __nv_bfloat162 t = {h10, h11}; hp1 = *(uint32_t*)&t; }
                *(uint32_t*)(Oh + (size_t)row * ldc + col) = hp0;
                *(uint32_t*)(Oh + (size_t)(row + 8) * ldc + col) = hp1;
                *(uint32_t*)(Ol + (size_t)row * ldc + col) = pack_bf2(l00, l01);
                *(uint32_t*)(Ol + (size_t)(row + 8) * ldc + col) = pack_bf2(l10, l11);
            }
        }
    }
}

// ---------------- fp32 -> bf16 hi/lo split ----------------
__global__ __launch_bounds__(256) void split_k(const float* __restrict__ in,
                                               bf16* __restrict__ h, bf16* __restrict__ l,
                                               int n4)
{
    int i = blockIdx.x * blockDim.x + threadIdx.x;
    if (i >= n4) return;
    float4 v = ((const float4*)in)[i];
    float vv[4] = {v.x, v.y, v.z, v.w};
    union { unsigned short u[4]; uint2 q; } hh, ll;
#pragma unroll
    for (int e = 0; e < 4; e++) {
        bf16 hb = __float2bfloat16(vv[e]);
        bf16 lb = __float2bfloat16(vv[e] - __bfloat162float(hb));
        hh.u[e] = *(unsigned short*)&hb;
        ll.u[e] = *(unsigned short*)&lb;
    }
    ((uint2*)h)[i] = hh.q;
    ((uint2*)l)[i] = ll.q;
}

// ---------------- concat bias [bq|bk|bv] ----------------
__global__ void concat_bias_k(const float* __restrict__ bq, const float* __restrict__ bk,
                              const float* __restrict__ bv, float* __restrict__ o)
{
    int i = blockIdx.x * blockDim.x + threadIdx.x;
    if (i >= QKV) return;
    float v;
    if (i < DIM) v = bq[i];
    else if (i < 2 * DIM) v = bk[i - DIM];
    else v = bv[i - 2 * DIM];
    o[i] = v;
}

// ---------------- transpose V[b][s][d](ldin) -> Vt[b][d][s] (hi & lo) ----------------
__global__ void transpose_k(const bf16* __restrict__ vh, const bf16* __restrict__ vl,
                            bf16* __restrict__ th, bf16* __restrict__ tl, int ldin)
{
    __shared__ bf16 sh[32][33], sl[32][33];
    const int z = blockIdx.z;
    const size_t ibi = (size_t)z * SEQ * ldin;
    const size_t ibo = (size_t)z * SEQ * DIM;
    const int d0 = blockIdx.x * 32, s0 = blockIdx.y * 32;
    const int tx = threadIdx.x, ty = threadIdx.y;
#pragma unroll
    for (int i = 0; i < 32; i += 8) {
        sh[ty + i][tx] = vh[ibi + (size_t)(s0 + ty + i) * ldin + d0 + tx];
        sl[ty + i][tx] = vl[ibi + (size_t)(s0 + ty + i) * ldin + d0 + tx];
    }
    __syncthreads();
#pragma unroll
    for (int i = 0; i < 32; i += 8) {
        th[ibo + (size_t)(d0 + ty + i) * SEQ + s0 + tx] = sh[tx][ty + i];
        tl[ibo + (size_t)(d0 + ty + i) * SEQ + s0 + tx] = sl[tx][ty + i];
    }
}

// ---------------- softmax: fp32 scores row -> P hi/lo bf16 ----------------
__global__ __launch_bounds__(256) void softmax_k(const float* __restrict__ S,
                                                 bf16* __restrict__ ph, bf16* __restrict__ pl)
{
    const size_t rb = (size_t)blockIdx.x * SEQ;
    const float* p = S + rb;
    const int tid = threadIdx.x;

    float4 v[4];
#pragma unroll
    for (int i = 0; i < 4; i++) v[i] = *(const float4*)(p + tid * 4 + i * 1024);

    float m = -INFINITY;
#pragma unroll
    for (int i = 0; i < 4; i++)
        m = fmaxf(m, fmaxf(fmaxf(v[i].x, v[i].y), fmaxf(v[i].z, v[i].w)));

    __shared__ float red[256];
    red[tid] = m; __syncthreads();
#pragma unroll
    for (int s = 128; s > 0; s >>= 1) {
        if (tid < s) red[tid] = fmaxf(red[tid], red[tid + s]);
        __syncthreads();
    }
    m = red[0]; __syncthreads();

    float sum = 0.0f;
#pragma unroll
    for (int i = 0; i < 4; i++) {
        v[i].x = __expf(v[i].x - m); v[i].y = __expf(v[i].y - m);
        v[i].z = __expf(v[i].z - m); v[i].w = __expf(v[i].w - m);
        sum += v[i].x + v[i].y + v[i].z + v[i].w;
    }
    red[tid] = sum; __syncthreads();
#pragma unroll
    for (int s = 128; s > 0; s >>= 1) {
        if (tid < s) red[tid] += red[tid + s];
        __syncthreads();
    }
    const float inv = 1.0f / red[0];

#pragma unroll
    for (int i = 0; i < 4; i++) {
        float vv[4] = {v[i].x * inv, v[i].y * inv, v[i].z * inv, v[i].w * inv};
        union { unsigned short u[4]; uint2 q; } hh, ll;
#pragma unroll
        for (int e = 0; e < 4; e++) {
            bf16 hb = __float2bfloat16(vv[e]);
            bf16 lb = __float2bfloat16(vv[e] - __bfloat162float(hb));
            hh.u[e] = *(unsigned short*)&hb;
            ll.u[e] = *(unsigned short*)&lb;
        }
        *(uint2*)(ph + rb + tid * 4 + i * 1024) = hh.q;
        *(uint2*)(pl + rb + tid * 4 + i * 1024) = ll.q;
    }
}

// ---------------- launch ----------------
extern "C" void kernel_launch(void* const* d_in, const int* in_sizes, int n_in,
                              void* d_out, int out_size)
{
    const float* x  = (const float*)d_in[0];
    const float* Wq = (const float*)d_in[1];
    const float* bq = (const float*)d_in[2];
    const float* Wk = (const float*)d_in[3];
    const float* bk = (const float*)d_in[4];
    const float* Wv = (const float*)d_in[5];
    const float* bv = (const float*)d_in[6];
    float* out = (float*)d_out;

    bf16 *xh, *xl, *wch, *wcl, *qkvh, *qkvl, *vth, *vtl, *pph, *ppl;
    float *sc, *bias;
    cudaGetSymbolAddress((void**)&xh, g_xh);     cudaGetSymbolAddress((void**)&xl, g_xl);
    cudaGetSymbolAddress((void**)&wch, g_wch);   cudaGetSymbolAddress((void**)&wcl, g_wcl);
    cudaGetSymbolAddress((void**)&qkvh, g_qkvh); cudaGetSymbolAddress((void**)&qkvl, g_qkvl);
    cudaGetSymbolAddress((void**)&vth, g_vth);   cudaGetSymbolAddress((void**)&vtl, g_vtl);
    cudaGetSymbolAddress((void**)&pph, g_ph);    cudaGetSymbolAddress((void**)&ppl, g_pl);
    cudaGetSymbolAddress((void**)&sc, g_s);      cudaGetSymbolAddress((void**)&bias, g_bias);

    cudaFuncSetAttribute(gemm_mma<0>, cudaFuncAttributeMaxDynamicSharedMemorySize, GEMM_SMEM);
    cudaFuncSetAttribute(gemm_mma<1>, cudaFuncAttributeMaxDynamicSharedMemorySize, GEMM_SMEM);

    const float scale = 1.0f / sqrtf((float)DIM);

    // 1. split inputs to bf16 hi/lo (weights into concatenated [Wq;Wk;Wv])
    split_k<<<(int)(NTD / 4 + 255) / 256, 256>>>(x, xh, xl, (int)(NTD / 4));
    split_k<<<(int)(WSZ / 4 + 255) / 256, 256>>>(Wq, wch, wcl, (int)(WSZ / 4));
    split_k<<<(int)(WSZ / 4 + 255) / 256, 256>>>(Wk, wch + WSZ, wcl + WSZ, (int)(WSZ / 4));
    split_k<<<(int)(WSZ / 4 + 255) / 256, 256>>>(Wv, wch + 2 * WSZ, wcl + 2 * WSZ, (int)(WSZ / 4));
    concat_bias_k<<<(QKV + 255) / 256, 256>>>(bq, bk, bv, bias);

    // 2. fused QKV projection: [16384, 2304] = X * Wc^T + bias  (hi/lo epilogue)
    gemm_mma<1><<<dim3(NTOK / BM, QKV / BN, 1), 256, GEMM_SMEM>>>(
        xh, xl, wch, wcl, nullptr, bias, qkvh, qkvl,
        DIM, DIM, DIM, QKV, 1.0f, 0, 0, 0);

    // 3. transpose V (qkv columns 1536..2303) -> Vt[b][d][s]
    transpose_k<<<dim3(DIM / 32, SEQ / 32, BATCH), dim3(32, 8)>>>(
        qkvh + 2 * DIM, qkvl + 2 * DIM, vth, vtl, QKV);

    // 4. scores[b] = scale * Q[b] K[b]^T   (q, k are qkv slices, ld = 2304)
    gemm_mma<0><<<dim3(SEQ / BM, SEQ / BN, BATCH), 256, GEMM_SMEM>>>(
        qkvh, qkvl, qkvh + DIM, qkvl + DIM, sc, nullptr, nullptr, nullptr,
        DIM, QKV, QKV, SEQ, scale,
        (size_t)SEQ * QKV, (size_t)SEQ * QKV, (size_t)SEQ * SEQ);

    // 5. softmax rows -> P hi/lo
    softmax_k<<<NTOK, 256>>>(sc, pph, ppl);

    // 6. out[b] = P[b] V[b]   (B operand = Vt, K-major over seq)
    gemm_mma<0><<<dim3(SEQ / BM, DIM / BN, BATCH), 256, GEMM_SMEM>>>(
        pph, ppl, vth, vtl, out, nullptr, nullptr, nullptr,
        SEQ, SEQ, SEQ, DIM, 1.0f,
        (size_t)SEQ * SEQ, (size_t)SEQ * DIM, (size_t)SEQ * DIM);

    (void)in_sizes; (void)n_in; (void)out_size;
}